// round 10
// baseline (speedup 1.0000x reference)
#include <cuda_runtime.h>
#include <cuda_bf16.h>
#include <cstdint>

constexpr int NN = 50000;
constexpr int EE = 800000;
constexpr int KC = 64;
constexpr int SCANB = 49;

// ---------------- device scratch ----------------
__device__ int   g_is64;
__device__ int   g_deg[NN];
__device__ int   g_cursor[NN];
__device__ int   g_ptr[NN + 1];
__device__ float g_invdeg[NN];
__device__ int   g_edges[EE];
__device__ int   g_part[SCANB];
__device__ int   g_boff[SCANB];

__device__ float g_a0f[(size_t)NN * 128];
__device__ float g_a1f[(size_t)NN * 128];
__device__ float g_hf [(size_t)NN * 256];
__device__ float g_amf[(size_t)NN * 256];
__device__ float g_h2f[(size_t)NN * 256];
__device__ float g_pq [(size_t)NN * 128];

__device__ __nv_bfloat16 g_WT0h[128 * 256];
__device__ __nv_bfloat16 g_WT0l[128 * 256];
__device__ __nv_bfloat16 g_WT1h[128 * 256];
__device__ __nv_bfloat16 g_WT1l[128 * 256];
__device__ __nv_bfloat16 g_WTmh[256 * 512];
__device__ __nv_bfloat16 g_WTml[256 * 512];
__device__ __nv_bfloat16 g_WTfh[128 * 256];
__device__ __nv_bfloat16 g_WTfl[128 * 256];
__device__ float         g_biasf[128];
__device__ float         g_zero[256];   // zero-initialized

// ---------------- edge dtype sniff ----------------
__global__ void sniff_kernel(const int* __restrict__ e32) {
    int is64 = 1;
    for (int i = 1; i < 64; i += 2)
        if (e32[i] != 0) { is64 = 0; break; }
    g_is64 = is64;
}
__device__ __forceinline__ int load_edge(const void* e, int idx) {
    if (g_is64) return (int)((const long long*)e)[idx];
    return ((const int*)e)[idx];
}

// ---------------- CSR build ----------------
__global__ void zero_kernel() {
    int i = blockIdx.x * blockDim.x + threadIdx.x;
    if (i < NN) { g_deg[i] = 0; g_cursor[i] = 0; }
}
__global__ void deg_kernel(const void* __restrict__ e) {
    int i = blockIdx.x * blockDim.x + threadIdx.x;
    if (i >= EE) return;
    atomicAdd(&g_deg[load_edge(e, EE + i)], 1);
}
__global__ void scan1_kernel() {
    __shared__ int sm[1024];
    int t = threadIdx.x;
    int i = blockIdx.x * 1024 + t;
    sm[t] = (i < NN) ? g_deg[i] : 0;
    __syncthreads();
    for (int off = 512; off; off >>= 1) {
        if (t < off) sm[t] += sm[t + off];
        __syncthreads();
    }
    if (t == 0) g_part[blockIdx.x] = sm[0];
}
__global__ void scan2_kernel() {
    if (threadIdx.x == 0) {
        int run = 0;
        for (int b = 0; b < SCANB; b++) { g_boff[b] = run; run += g_part[b]; }
        g_ptr[NN] = EE;
    }
}
__global__ void scan3_kernel() {
    __shared__ int sm[1024];
    int t = threadIdx.x;
    int i = blockIdx.x * 1024 + t;
    int v = (i < NN) ? g_deg[i] : 0;
    sm[t] = v;
    __syncthreads();
    for (int off = 1; off < 1024; off <<= 1) {
        int u = (t >= off) ? sm[t - off] : 0;
        __syncthreads();
        if (t >= off) sm[t] += u;
        __syncthreads();
    }
    if (i < NN) {
        g_ptr[i] = g_boff[blockIdx.x] + sm[t] - v;
        g_invdeg[i] = 1.0f / (float)max(v, 1);
    }
}
__global__ void scatter_kernel(const void* __restrict__ e) {
    int i = blockIdx.x * blockDim.x + threadIdx.x;
    if (i >= EE) return;
    int src = load_edge(e, i);
    int dst = load_edge(e, EE + i);
    g_edges[g_ptr[dst] + atomicAdd(&g_cursor[dst], 1)] = src;
}

// ---------------- weight prep ----------------
__device__ __forceinline__ void split2(float v, __nv_bfloat16& h, __nv_bfloat16& l) {
    h = __float2bfloat16(v);
    l = __float2bfloat16(v - __bfloat162float(h));
}
__global__ void wprep_kernel(const float* __restrict__ Wl0, const float* __restrict__ Wr0,
                             const float* __restrict__ Wl1, const float* __restrict__ Wr1,
                             const float* __restrict__ Wlm, const float* __restrict__ Wrm,
                             const float* __restrict__ Wlo, const float* __restrict__ Wro,
                             const float* __restrict__ bo) {
    int i = blockIdx.x * blockDim.x + threadIdx.x;
    if (i < 128 * 256) {
        int n = i >> 8, k = i & 255;
        float w0 = (k < 128) ? Wl0[k * 128 + n] : Wr0[(k - 128) * 128 + n];
        float w1 = (k < 128) ? Wl1[k * 128 + n] : Wr1[(k - 128) * 128 + n];
        split2(w0, g_WT0h[i], g_WT0l[i]);
        split2(w1, g_WT1h[i], g_WT1l[i]);
        float wf = (n < 64) ? Wlo[k * 64 + n] : Wro[k * 64 + (n - 64)];
        split2(wf, g_WTfh[i], g_WTfl[i]);
        if (i < 128) g_biasf[i] = (i < 64) ? 0.f : bo[i - 64];
    }
    int j = i - 128 * 256;
    if (j >= 0 && j < 256 * 512) {
        int n = j >> 9, k = j & 511;
        float w = (k < 256) ? Wlm[k * 256 + n] : Wrm[(k - 256) * 256 + n];
        split2(w, g_WTmh[j], g_WTml[j]);
    }
}

// ---------------- aggregation ----------------
__global__ __launch_bounds__(128) void agg_xx_kernel(
    const float* __restrict__ x0, const float* __restrict__ x1) {
    __shared__ float red0[4][128];
    __shared__ float red1[4][128];
    int node = blockIdx.x;
    int t = threadIdx.x;
    int lane = t & 31, w = t >> 5;
    int s = g_ptr[node], e = g_ptr[node + 1];
    float4 a0 = make_float4(0.f, 0.f, 0.f, 0.f), a1 = a0;
    for (int i = s + w; i < e; i += 4) {
        int src = g_edges[i];
        float4 v0 = __ldg((const float4*)(x0 + (size_t)src * 128) + lane);
        float4 v1 = __ldg((const float4*)(x1 + (size_t)src * 128) + lane);
        a0.x += v0.x; a0.y += v0.y; a0.z += v0.z; a0.w += v0.w;
        a1.x += v1.x; a1.y += v1.y; a1.z += v1.z; a1.w += v1.w;
    }
    *(float4*)&red0[w][lane * 4] = a0;
    *(float4*)&red1[w][lane * 4] = a1;
    __syncthreads();
    float inv = g_invdeg[node];
    float s0 = (red0[0][t] + red0[1][t]) + (red0[2][t] + red0[3][t]);
    float s1 = (red1[0][t] + red1[1][t]) + (red1[2][t] + red1[3][t]);
    g_a0f[(size_t)node * 128 + t] = s0 * inv;
    g_a1f[(size_t)node * 128 + t] = s1 * inv;
}

__global__ __launch_bounds__(256) void agg_mid_kernel(const float* __restrict__ X) {
    __shared__ float red[4][256];
    int node = blockIdx.x;
    int t = threadIdx.x;
    int lane = t & 31, w = t >> 5;
    int el = w >> 1, half = w & 1;
    int s = g_ptr[node], e = g_ptr[node + 1];
    float4 a = make_float4(0.f, 0.f, 0.f, 0.f);
    for (int i = s + el; i < e; i += 4) {
        int src = g_edges[i];
        float4 v = __ldg((const float4*)(X + (size_t)src * 256) + half * 32 + lane);
        a.x += v.x; a.y += v.y; a.z += v.z; a.w += v.w;
    }
    *(float4*)&red[el][half * 128 + lane * 4] = a;
    __syncthreads();
    float sum = (red[0][t] + red[1][t]) + (red[2][t] + red[3][t]);
    g_amf[(size_t)node * 256 + t] = sum * g_invdeg[node];
}

__global__ __launch_bounds__(64) void final_kernel(float* __restrict__ out) {
    __shared__ float red[4][64];
    int node = blockIdx.x;
    int t = threadIdx.x;
    int el = t >> 4, c4 = t & 15;
    int s = g_ptr[node], e = g_ptr[node + 1];
    float4 a = make_float4(0.f, 0.f, 0.f, 0.f);
    for (int i = s + el; i < e; i += 4) {
        int src = g_edges[i];
        float4 v = __ldg((const float4*)(g_pq + (size_t)src * 128) + c4);
        a.x += v.x; a.y += v.y; a.z += v.z; a.w += v.w;
    }
    *(float4*)&red[el][c4 * 4] = a;
    __syncthreads();
    float sum = (red[0][t] + red[1][t]) + (red[2][t] + red[3][t]);
    out[(size_t)node * 64 + t] = sum * g_invdeg[node] + g_pq[(size_t)node * 128 + 64 + t];
}

// ---------------- mma.sync split-bf16 GEMM ----------------
// C[row, n0+cl] = sum_k A[row, k] * WT[n0+cl, k] (+ Add[row, co+n0+cl]) (+ bias) (relu)
// WT row stride = Kstride (K-range preselected by pointer offset). blockIdx.z picks set a/b.
#define PAD 72
#define AH_OFF 0
#define AL_OFF (128 * PAD * 2)
#define BH_OFF (2 * 128 * PAD * 2)
#define BL_OFF (3 * 128 * PAD * 2)
#define SMEM_SZ (4 * 128 * PAD * 2)

__device__ __forceinline__ void mma16816(float* d, const uint32_t* a, const uint32_t* b) {
    asm volatile(
        "mma.sync.aligned.m16n8k16.row.col.f32.bf16.bf16.f32 "
        "{%0,%1,%2,%3}, {%4,%5,%6,%7}, {%8,%9}, {%0,%1,%2,%3};"
        : "+f"(d[0]), "+f"(d[1]), "+f"(d[2]), "+f"(d[3])
        : "r"(a[0]), "r"(a[1]), "r"(a[2]), "r"(a[3]), "r"(b[0]), "r"(b[1]));
}

__global__ __launch_bounds__(512) void gemm_mma(
    const float* __restrict__ Aa,
    const __nv_bfloat16* __restrict__ WTha, const __nv_bfloat16* __restrict__ WTla,
    const float* __restrict__ biasa, const float* __restrict__ Adda, int coa,
    const float* __restrict__ Ab,
    const __nv_bfloat16* __restrict__ WThb, const __nv_bfloat16* __restrict__ WTlb,
    const float* __restrict__ biasb, const float* __restrict__ Addb, int cob,
    int lda, int Ktot, int Kstride,
    int relu, float* __restrict__ O, int ldo)
{
    extern __shared__ char smem[];
    __nv_bfloat16* Ash = (__nv_bfloat16*)(smem + AH_OFF);
    __nv_bfloat16* Asl = (__nv_bfloat16*)(smem + AL_OFF);
    __nv_bfloat16* Bsh = (__nv_bfloat16*)(smem + BH_OFF);
    __nv_bfloat16* Bsl = (__nv_bfloat16*)(smem + BL_OFF);

    const float* A = Aa;
    const __nv_bfloat16* WTh = WTha; const __nv_bfloat16* WTl = WTla;
    const float* bias = biasa; const float* Add = Adda; int co = coa;
    if (blockIdx.z) { A = Ab; WTh = WThb; WTl = WTlb; bias = biasb; Add = Addb; co = cob; }

    int tid = threadIdx.x;
    int wid = tid >> 5;
    int lane = tid & 31;
    int g = lane >> 2, tig = lane & 3;
    int wm = wid >> 2, wn = wid & 3;
    int row0 = blockIdx.x * 128;
    int n0 = blockIdx.y * 128;

    const __nv_bfloat16* WThB = WTh + (size_t)n0 * Kstride;
    const __nv_bfloat16* WTlB = WTl + (size_t)n0 * Kstride;

    float acc[2][4][4];
#pragma unroll
    for (int mt = 0; mt < 2; mt++)
#pragma unroll
        for (int nt = 0; nt < 4; nt++)
#pragma unroll
            for (int q = 0; q < 4; q++) acc[mt][nt][q] = 0.f;

    float4 aReg[4];
    uint4  bReg[4];
    int aRow[4];
#pragma unroll
    for (int it = 0; it < 4; it++) {
        int idx = tid + it * 512;
        aRow[it] = row0 + (idx >> 4);
    }

    auto loadA = [&](int c) {
        int kt = c * KC;
#pragma unroll
        for (int it = 0; it < 4; it++) {
            int idx = tid + it * 512;
            int c4 = idx & 15;
            float4 v = make_float4(0.f, 0.f, 0.f, 0.f);
            if (aRow[it] < NN)
                v = __ldg((const float4*)(A + (size_t)aRow[it] * lda + kt) + c4);
            aReg[it] = v;
        }
    };
    auto loadB = [&](int c) {
        int kt = c * KC;
#pragma unroll
        for (int it = 0; it < 2; it++) {
            int idx = tid + it * 512;
            int r = idx >> 3, c8 = idx & 7;
            bReg[it]     = *(const uint4*)(WThB + (size_t)r * Kstride + kt + c8 * 8);
            bReg[it + 2] = *(const uint4*)(WTlB + (size_t)r * Kstride + kt + c8 * 8);
        }
    };

    int nchunks = Ktot / KC;
    loadA(0);
    loadB(0);
    for (int c = 0; c < nchunks; c++) {
        __syncthreads();
#pragma unroll
        for (int it = 0; it < 4; it++) {
            int idx = tid + it * 512;
            int r = idx >> 4, c4 = idx & 15;
            float4 v = aReg[it];
            __nv_bfloat162 h01, h23, l01, l23;
            h01.x = __float2bfloat16(v.x); l01.x = __float2bfloat16(v.x - __bfloat162float(h01.x));
            h01.y = __float2bfloat16(v.y); l01.y = __float2bfloat16(v.y - __bfloat162float(h01.y));
            h23.x = __float2bfloat16(v.z); l23.x = __float2bfloat16(v.z - __bfloat162float(h23.x));
            h23.y = __float2bfloat16(v.w); l23.y = __float2bfloat16(v.w - __bfloat162float(h23.y));
            uint2 uh, ul;
            uh.x = *(uint32_t*)&h01; uh.y = *(uint32_t*)&h23;
            ul.x = *(uint32_t*)&l01; ul.y = *(uint32_t*)&l23;
            *(uint2*)&Ash[r * PAD + c4 * 4] = uh;
            *(uint2*)&Asl[r * PAD + c4 * 4] = ul;
        }
#pragma unroll
        for (int it = 0; it < 2; it++) {
            int idx = tid + it * 512;
            int r = idx >> 3, c8 = idx & 7;
            *(uint4*)&Bsh[r * PAD + c8 * 8] = bReg[it];
            *(uint4*)&Bsl[r * PAD + c8 * 8] = bReg[it + 2];
        }
        __syncthreads();
        if (c + 1 < nchunks) { loadA(c + 1); loadB(c + 1); }

#pragma unroll
        for (int ks = 0; ks < KC / 16; ks++) {
            int kk = ks * 16;
            uint32_t ah[2][4], al[2][4];
#pragma unroll
            for (int mt = 0; mt < 2; mt++) {
                int ar = wm * 32 + mt * 16 + g;
                int cA = kk + tig * 2;
                ah[mt][0] = *(const uint32_t*)&Ash[ar * PAD + cA];
                ah[mt][1] = *(const uint32_t*)&Ash[(ar + 8) * PAD + cA];
                ah[mt][2] = *(const uint32_t*)&Ash[ar * PAD + cA + 8];
                ah[mt][3] = *(const uint32_t*)&Ash[(ar + 8) * PAD + cA + 8];
                al[mt][0] = *(const uint32_t*)&Asl[ar * PAD + cA];
                al[mt][1] = *(const uint32_t*)&Asl[(ar + 8) * PAD + cA];
                al[mt][2] = *(const uint32_t*)&Asl[ar * PAD + cA + 8];
                al[mt][3] = *(const uint32_t*)&Asl[(ar + 8) * PAD + cA + 8];
            }
#pragma unroll
            for (int nt = 0; nt < 4; nt++) {
                int bn = wn * 32 + nt * 8 + g;
                int cB = kk + tig * 2;
                uint32_t bh[2], bl[2];
                bh[0] = *(const uint32_t*)&Bsh[bn * PAD + cB];
                bh[1] = *(const uint32_t*)&Bsh[bn * PAD + cB + 8];
                bl[0] = *(const uint32_t*)&Bsl[bn * PAD + cB];
                bl[1] = *(const uint32_t*)&Bsl[bn * PAD + cB + 8];
#pragma unroll
                for (int mt = 0; mt < 2; mt++) {
                    mma16816(acc[mt][nt], ah[mt], bh);
                    mma16816(acc[mt][nt], ah[mt], bl);
                    mma16816(acc[mt][nt], al[mt], bh);
                }
            }
        }
    }

#pragma unroll
    for (int mt = 0; mt < 2; mt++) {
        int r1 = row0 + wm * 32 + mt * 16 + g;
        int r2 = r1 + 8;
#pragma unroll
        for (int nt = 0; nt < 4; nt++) {
            int cl = wn * 32 + nt * 8 + tig * 2;
            int cg = n0 + cl;
            float b0v = bias[cg], b1v = bias[cg + 1];
            float v00 = acc[mt][nt][0] + b0v, v01 = acc[mt][nt][1] + b1v;
            float v10 = acc[mt][nt][2] + b0v, v11 = acc[mt][nt][3] + b1v;
            if (Add) {
                if (r1 < NN) {
                    float2 q = *(const float2*)&Add[(size_t)r1 * ldo + co + cg];
                    v00 += q.x; v01 += q.y;
                }
                if (r2 < NN) {
                    float2 q = *(const float2*)&Add[(size_t)r2 * ldo + co + cg];
                    v10 += q.x; v11 += q.y;
                }
            }
            if (relu) {
                v00 = fmaxf(v00, 0.f); v01 = fmaxf(v01, 0.f);
                v10 = fmaxf(v10, 0.f); v11 = fmaxf(v11, 0.f);
            }
            if (r1 < NN) *(float2*)&O[(size_t)r1 * ldo + co + cg] = make_float2(v00, v01);
            if (r2 < NN) *(float2*)&O[(size_t)r2 * ldo + co + cg] = make_float2(v10, v11);
        }
    }
}

// ---------------- launch ----------------
extern "C" void kernel_launch(void* const* d_in, const int* in_sizes, int n_in,
                              void* d_out, int out_size) {
    const float* x0  = (const float*)d_in[0];
    const float* x1  = (const float*)d_in[1];
    const void*  eix = d_in[2];
    const float* Wl0 = (const float*)d_in[3];
    const float* Wr0 = (const float*)d_in[4];
    const float* b0  = (const float*)d_in[5];
    const float* Wl1 = (const float*)d_in[6];
    const float* Wr1 = (const float*)d_in[7];
    const float* b1  = (const float*)d_in[8];
    const float* Wlm = (const float*)d_in[9];
    const float* Wrm = (const float*)d_in[10];
    const float* bm  = (const float*)d_in[11];
    const float* Wlo = (const float*)d_in[12];
    const float* Wro = (const float*)d_in[13];
    const float* bo  = (const float*)d_in[14];
    float* out = (float*)d_out;

    cudaFuncSetAttribute(gemm_mma, cudaFuncAttributeMaxDynamicSharedMemorySize, SMEM_SZ);

    float *a0f, *a1f, *hf, *amf, *h2f, *pq, *biasf, *zero;
    __nv_bfloat16 *WT0h, *WT0l, *WT1h, *WT1l, *WTmh, *WTml, *WTfh, *WTfl;
    cudaGetSymbolAddress((void**)&a0f, g_a0f);
    cudaGetSymbolAddress((void**)&a1f, g_a1f);
    cudaGetSymbolAddress((void**)&hf,  g_hf);
    cudaGetSymbolAddress((void**)&amf, g_amf);
    cudaGetSymbolAddress((void**)&h2f, g_h2f);
    cudaGetSymbolAddress((void**)&pq,  g_pq);
    cudaGetSymbolAddress((void**)&biasf, g_biasf);
    cudaGetSymbolAddress((void**)&zero,  g_zero);
    cudaGetSymbolAddress((void**)&WT0h, g_WT0h); cudaGetSymbolAddress((void**)&WT0l, g_WT0l);
    cudaGetSymbolAddress((void**)&WT1h, g_WT1h); cudaGetSymbolAddress((void**)&WT1l, g_WT1l);
    cudaGetSymbolAddress((void**)&WTmh, g_WTmh); cudaGetSymbolAddress((void**)&WTml, g_WTml);
    cudaGetSymbolAddress((void**)&WTfh, g_WTfh); cudaGetSymbolAddress((void**)&WTfl, g_WTfl);

    // side stream + fork/join events (created per call; never destroyed — bounded leak,
    // host-side only, keeps captured graph nodes valid)
    cudaStream_t s2;
    cudaStreamCreateWithFlags(&s2, cudaStreamNonBlocking);
    cudaEvent_t evFork, evJ1, evG, evJ2;
    cudaEventCreateWithFlags(&evFork, cudaEventDisableTiming);
    cudaEventCreateWithFlags(&evJ1, cudaEventDisableTiming);
    cudaEventCreateWithFlags(&evG, cudaEventDisableTiming);
    cudaEventCreateWithFlags(&evJ2, cudaEventDisableTiming);

    const int GX = (NN + 127) / 128;  // 391

    // fork side stream off capture root
    cudaEventRecord(evFork, 0);
    cudaStreamWaitEvent(s2, evFork, 0);

    // ---- stream 0: CSR build + first aggregation (memory-bound chain) ----
    sniff_kernel<<<1, 1>>>((const int*)eix);
    zero_kernel<<<(NN + 255) / 256, 256>>>();
    deg_kernel<<<(EE + 255) / 256, 256>>>(eix);
    scan1_kernel<<<SCANB, 1024>>>();
    scan2_kernel<<<1, 32>>>();
    scan3_kernel<<<SCANB, 1024>>>();
    scatter_kernel<<<(EE + 255) / 256, 256>>>(eix);
    agg_xx_kernel<<<NN, 128>>>(x0, x1);

    // ---- stream s2 (concurrent): weight prep + self-GEMMs S0/S1 ----
    wprep_kernel<<<(128 * 256 + 256 * 512 + 255) / 256, 256, 0, s2>>>(
        Wl0, Wr0, Wl1, Wr1, Wlm, Wrm, Wlo, Wro, bo);
    // S01: hf[:, 0:128] = x0@Wr0 + b0 ; hf[:, 128:256] = x1@Wr1 + b1  (no relu)
    gemm_mma<<<dim3(GX, 1, 2), 512, SMEM_SZ, s2>>>(
        x0, WT0h + 128, WT0l + 128, b0, nullptr, 0,
        x1, WT1h + 128, WT1l + 128, b1, nullptr, 128,
        128, 128, 256, 0, hf, 256);
    cudaEventRecord(evJ1, s2);

    // ---- join: G01: hf = relu(agg@Wl + hf) ----
    cudaStreamWaitEvent(0, evJ1, 0);
    gemm_mma<<<dim3(GX, 1, 2), 512, SMEM_SZ>>>(
        a0f, WT0h, WT0l, zero, hf, 0,
        a1f, WT1h, WT1l, zero, hf, 128,
        128, 128, 256, 1, hf, 256);
    cudaEventRecord(evG, 0);

    // ---- stream 0: agg_mid (memory)  ∥  s2: Sm = hf@Wrm + bm (compute) ----
    agg_mid_kernel<<<NN, 256>>>(hf);
    cudaStreamWaitEvent(s2, evG, 0);
    gemm_mma<<<dim3(GX, 2, 1), 512, SMEM_SZ, s2>>>(
        hf, WTmh + 256, WTml + 256, bm, nullptr, 0,
        hf, WTmh + 256, WTml + 256, bm, nullptr, 0,
        256, 256, 512, 0, h2f, 256);
    cudaEventRecord(evJ2, s2);

    // ---- join: Gm: h2f = relu(amf@Wlm + h2f) ----
    cudaStreamWaitEvent(0, evJ2, 0);
    gemm_mma<<<dim3(GX, 2, 1), 512, SMEM_SZ>>>(
        amf, WTmh, WTml, zero, h2f, 0,
        amf, WTmh, WTml, zero, h2f, 0,
        256, 256, 512, 1, h2f, 256);

    // ---- final conv (project-then-aggregate) ----
    gemm_mma<<<dim3(GX, 1, 1), 512, SMEM_SZ>>>(
        h2f, WTfh, WTfl, biasf, nullptr, 0,
        h2f, WTfh, WTfl, biasf, nullptr, 0,
        256, 256, 256, 0, pq, 128);
    final_kernel<<<NN, 64>>>(out);
}

// round 11
// speedup vs baseline: 1.0973x; 1.0973x over previous
#include <cuda_runtime.h>
#include <cuda_bf16.h>
#include <cstdint>

constexpr int NN = 50000;
constexpr int EE = 800000;
constexpr int KC = 64;
constexpr int SCANB = 49;

// ---------------- device scratch ----------------
__device__ int   g_is64;
__device__ int   g_deg[NN];
__device__ int   g_cursor[NN];
__device__ int   g_ptr[NN + 1];
__device__ float g_invdeg[NN];
__device__ int   g_edges[EE];
__device__ int   g_part[SCANB];
__device__ int   g_boff[SCANB];

__device__ float g_a0f[(size_t)NN * 128];
__device__ float g_a1f[(size_t)NN * 128];
__device__ float g_hf [(size_t)NN * 256];
__device__ float g_amf[(size_t)NN * 256];
__device__ float g_h2f[(size_t)NN * 256];
__device__ float g_pq [(size_t)NN * 128];

__device__ __nv_bfloat16 g_WT0h[128 * 256];
__device__ __nv_bfloat16 g_WT0l[128 * 256];
__device__ __nv_bfloat16 g_WT1h[128 * 256];
__device__ __nv_bfloat16 g_WT1l[128 * 256];
__device__ __nv_bfloat16 g_WTmh[256 * 512];
__device__ __nv_bfloat16 g_WTml[256 * 512];
__device__ __nv_bfloat16 g_WTfh[128 * 256];
__device__ __nv_bfloat16 g_WTfl[128 * 256];
__device__ float         g_biasf[128];

// ---------------- edge dtype sniff ----------------
__global__ void sniff_kernel(const int* __restrict__ e32) {
    int is64 = 1;
    for (int i = 1; i < 64; i += 2)
        if (e32[i] != 0) { is64 = 0; break; }
    g_is64 = is64;
}
__device__ __forceinline__ int load_edge(const void* e, int idx) {
    if (g_is64) return (int)((const long long*)e)[idx];
    return ((const int*)e)[idx];
}

// ---------------- CSR build ----------------
__global__ void zero_kernel() {
    int i = blockIdx.x * blockDim.x + threadIdx.x;
    if (i < NN) { g_deg[i] = 0; g_cursor[i] = 0; }
}
__global__ void deg_kernel(const void* __restrict__ e) {
    int i = blockIdx.x * blockDim.x + threadIdx.x;
    if (i >= EE) return;
    atomicAdd(&g_deg[load_edge(e, EE + i)], 1);
}
__global__ void scan1_kernel() {
    __shared__ int sm[1024];
    int t = threadIdx.x;
    int i = blockIdx.x * 1024 + t;
    sm[t] = (i < NN) ? g_deg[i] : 0;
    __syncthreads();
    for (int off = 512; off; off >>= 1) {
        if (t < off) sm[t] += sm[t + off];
        __syncthreads();
    }
    if (t == 0) g_part[blockIdx.x] = sm[0];
}
__global__ void scan2_kernel() {
    if (threadIdx.x == 0) {
        int run = 0;
        for (int b = 0; b < SCANB; b++) { g_boff[b] = run; run += g_part[b]; }
        g_ptr[NN] = EE;
    }
}
__global__ void scan3_kernel() {
    __shared__ int sm[1024];
    int t = threadIdx.x;
    int i = blockIdx.x * 1024 + t;
    int v = (i < NN) ? g_deg[i] : 0;
    sm[t] = v;
    __syncthreads();
    for (int off = 1; off < 1024; off <<= 1) {
        int u = (t >= off) ? sm[t - off] : 0;
        __syncthreads();
        if (t >= off) sm[t] += u;
        __syncthreads();
    }
    if (i < NN) {
        g_ptr[i] = g_boff[blockIdx.x] + sm[t] - v;
        g_invdeg[i] = 1.0f / (float)max(v, 1);
    }
}
__global__ void scatter_kernel(const void* __restrict__ e) {
    int i = blockIdx.x * blockDim.x + threadIdx.x;
    if (i >= EE) return;
    int src = load_edge(e, i);
    int dst = load_edge(e, EE + i);
    g_edges[g_ptr[dst] + atomicAdd(&g_cursor[dst], 1)] = src;
}

// ---------------- weight prep ----------------
__device__ __forceinline__ void split2(float v, __nv_bfloat16& h, __nv_bfloat16& l) {
    h = __float2bfloat16(v);
    l = __float2bfloat16(v - __bfloat162float(h));
}
__global__ void wprep_kernel(const float* __restrict__ Wl0, const float* __restrict__ Wr0,
                             const float* __restrict__ Wl1, const float* __restrict__ Wr1,
                             const float* __restrict__ Wlm, const float* __restrict__ Wrm,
                             const float* __restrict__ Wlo, const float* __restrict__ Wro,
                             const float* __restrict__ bo) {
    int i = blockIdx.x * blockDim.x + threadIdx.x;
    if (i < 128 * 256) {
        int n = i >> 8, k = i & 255;
        float w0 = (k < 128) ? Wl0[k * 128 + n] : Wr0[(k - 128) * 128 + n];
        float w1 = (k < 128) ? Wl1[k * 128 + n] : Wr1[(k - 128) * 128 + n];
        split2(w0, g_WT0h[i], g_WT0l[i]);
        split2(w1, g_WT1h[i], g_WT1l[i]);
        float wf = (n < 64) ? Wlo[k * 64 + n] : Wro[k * 64 + (n - 64)];
        split2(wf, g_WTfh[i], g_WTfl[i]);
        if (i < 128) g_biasf[i] = (i < 64) ? 0.f : bo[i - 64];
    }
    int j = i - 128 * 256;
    if (j >= 0 && j < 256 * 512) {
        int n = j >> 9, k = j & 511;
        float w = (k < 256) ? Wlm[k * 256 + n] : Wrm[(k - 256) * 256 + n];
        split2(w, g_WTmh[j], g_WTml[j]);
    }
}

// ---------------- aggregation ----------------
__global__ __launch_bounds__(128) void agg_xx_kernel(
    const float* __restrict__ x0, const float* __restrict__ x1) {
    __shared__ float red0[4][128];
    __shared__ float red1[4][128];
    int node = blockIdx.x;
    int t = threadIdx.x;
    int lane = t & 31, w = t >> 5;
    int s = g_ptr[node], e = g_ptr[node + 1];
    float4 a0 = make_float4(0.f, 0.f, 0.f, 0.f), a1 = a0;
    for (int i = s + w; i < e; i += 4) {
        int src = g_edges[i];
        float4 v0 = __ldg((const float4*)(x0 + (size_t)src * 128) + lane);
        float4 v1 = __ldg((const float4*)(x1 + (size_t)src * 128) + lane);
        a0.x += v0.x; a0.y += v0.y; a0.z += v0.z; a0.w += v0.w;
        a1.x += v1.x; a1.y += v1.y; a1.z += v1.z; a1.w += v1.w;
    }
    *(float4*)&red0[w][lane * 4] = a0;
    *(float4*)&red1[w][lane * 4] = a1;
    __syncthreads();
    float inv = g_invdeg[node];
    float s0 = (red0[0][t] + red0[1][t]) + (red0[2][t] + red0[3][t]);
    float s1 = (red1[0][t] + red1[1][t]) + (red1[2][t] + red1[3][t]);
    g_a0f[(size_t)node * 128 + t] = s0 * inv;
    g_a1f[(size_t)node * 128 + t] = s1 * inv;
}

__global__ __launch_bounds__(256) void agg_mid_kernel(const float* __restrict__ X) {
    __shared__ float red[4][256];
    int node = blockIdx.x;
    int t = threadIdx.x;
    int lane = t & 31, w = t >> 5;
    int el = w >> 1, half = w & 1;
    int s = g_ptr[node], e = g_ptr[node + 1];
    float4 a = make_float4(0.f, 0.f, 0.f, 0.f);
    for (int i = s + el; i < e; i += 4) {
        int src = g_edges[i];
        float4 v = __ldg((const float4*)(X + (size_t)src * 256) + half * 32 + lane);
        a.x += v.x; a.y += v.y; a.z += v.z; a.w += v.w;
    }
    *(float4*)&red[el][half * 128 + lane * 4] = a;
    __syncthreads();
    float sum = (red[0][t] + red[1][t]) + (red[2][t] + red[3][t]);
    g_amf[(size_t)node * 256 + t] = sum * g_invdeg[node];
}

__global__ __launch_bounds__(64) void final_kernel(float* __restrict__ out) {
    __shared__ float red[4][64];
    int node = blockIdx.x;
    int t = threadIdx.x;
    int el = t >> 4, c4 = t & 15;
    int s = g_ptr[node], e = g_ptr[node + 1];
    float4 a = make_float4(0.f, 0.f, 0.f, 0.f);
    for (int i = s + el; i < e; i += 4) {
        int src = g_edges[i];
        float4 v = __ldg((const float4*)(g_pq + (size_t)src * 128) + c4);
        a.x += v.x; a.y += v.y; a.z += v.z; a.w += v.w;
    }
    *(float4*)&red[el][c4 * 4] = a;
    __syncthreads();
    float sum = (red[0][t] + red[1][t]) + (red[2][t] + red[3][t]);
    out[(size_t)node * 64 + t] = sum * g_invdeg[node] + g_pq[(size_t)node * 128 + 64 + t];
}

// ---------------- mma.sync split-bf16 GEMM, double-buffered SMEM ----------------
// C[row, n] = sum_k A[row, k] * WT[n, k]; A = (A1|A2) fp32 concat over k.
// fp32 emulated: Ah*Bh + Ah*Bl + Al*Bh, fp32 accumulate.
// 512 threads = 16 warps (4x4); CTA tile 128x128; warp tile 32x32.
// Two SMEM stages: mma reads stage c&1 while chunk c+1 is stored to the other
// stage; ONE __syncthreads per chunk (regs already cap us at 1 CTA/SM, so the
// doubled SMEM footprint costs nothing).
#define PAD 72
#define AH_OFF 0
#define AL_OFF (128 * PAD * 2)
#define BH_OFF (2 * 128 * PAD * 2)
#define BL_OFF (3 * 128 * PAD * 2)
#define STAGE  (4 * 128 * PAD * 2)
#define SMEM_SZ (2 * STAGE)

__device__ __forceinline__ void mma16816(float* d, const uint32_t* a, const uint32_t* b) {
    asm volatile(
        "mma.sync.aligned.m16n8k16.row.col.f32.bf16.bf16.f32 "
        "{%0,%1,%2,%3}, {%4,%5,%6,%7}, {%8,%9}, {%0,%1,%2,%3};"
        : "+f"(d[0]), "+f"(d[1]), "+f"(d[2]), "+f"(d[3])
        : "r"(a[0]), "r"(a[1]), "r"(a[2]), "r"(a[3]), "r"(b[0]), "r"(b[1]));
}

__global__ __launch_bounds__(512) void gemm_mma(
    const float* __restrict__ A1a, const float* __restrict__ A2a,
    const __nv_bfloat16* __restrict__ WTha, const __nv_bfloat16* __restrict__ WTla,
    const float* __restrict__ biasa, int coa,
    const float* __restrict__ A1b, const float* __restrict__ A2b,
    const __nv_bfloat16* __restrict__ WThb, const __nv_bfloat16* __restrict__ WTlb,
    const float* __restrict__ biasb, int cob,
    int lda1, int lda2, int K1, int Ktot,
    int relu, float* __restrict__ O, int ldo)
{
    extern __shared__ char smem[];

    const float* A1 = A1a; const float* A2 = A2a;
    const __nv_bfloat16* WTh = WTha; const __nv_bfloat16* WTl = WTla;
    const float* bias = biasa; int co = coa;
    if (blockIdx.z) { A1 = A1b; A2 = A2b; WTh = WThb; WTl = WTlb; bias = biasb; co = cob; }

    int tid = threadIdx.x;
    int wid = tid >> 5;
    int lane = tid & 31;
    int g = lane >> 2, tig = lane & 3;
    int wm = wid >> 2, wn = wid & 3;
    int row0 = blockIdx.x * 128;
    int n0 = blockIdx.y * 128;

    const __nv_bfloat16* WThB = WTh + (size_t)n0 * Ktot;
    const __nv_bfloat16* WTlB = WTl + (size_t)n0 * Ktot;

    float acc[2][4][4];
#pragma unroll
    for (int mt = 0; mt < 2; mt++)
#pragma unroll
        for (int nt = 0; nt < 4; nt++)
#pragma unroll
            for (int q = 0; q < 4; q++) acc[mt][nt][q] = 0.f;

    float4 aReg[4];
    uint4  bReg[4];
    int aRow[4];
#pragma unroll
    for (int it = 0; it < 4; it++) {
        int idx = tid + it * 512;
        aRow[it] = row0 + (idx >> 4);
    }

    auto loadA = [&](int c) {
        int kt = c * KC;
        const float* A; int lda, kb;
        if (kt < K1) { A = A1; lda = lda1; kb = kt; }
        else         { A = A2; lda = lda2; kb = kt - K1; }
#pragma unroll
        for (int it = 0; it < 4; it++) {
            int idx = tid + it * 512;
            int c4 = idx & 15;
            float4 v = make_float4(0.f, 0.f, 0.f, 0.f);
            if (aRow[it] < NN)
                v = __ldg((const float4*)(A + (size_t)aRow[it] * lda + kb) + c4);
            aReg[it] = v;
        }
    };
    auto loadB = [&](int c) {
        int kt = c * KC;
#pragma unroll
        for (int it = 0; it < 2; it++) {
            int idx = tid + it * 512;
            int r = idx >> 3, c8 = idx & 7;
            bReg[it]     = *(const uint4*)(WThB + (size_t)r * Ktot + kt + c8 * 8);
            bReg[it + 2] = *(const uint4*)(WTlB + (size_t)r * Ktot + kt + c8 * 8);
        }
    };
    auto storeStage = [&](int s) {
        char* base = smem + s * STAGE;
        __nv_bfloat16* Ash = (__nv_bfloat16*)(base + AH_OFF);
        __nv_bfloat16* Asl = (__nv_bfloat16*)(base + AL_OFF);
        __nv_bfloat16* Bsh = (__nv_bfloat16*)(base + BH_OFF);
        __nv_bfloat16* Bsl = (__nv_bfloat16*)(base + BL_OFF);
#pragma unroll
        for (int it = 0; it < 4; it++) {
            int idx = tid + it * 512;
            int r = idx >> 4, c4 = idx & 15;
            float4 v = aReg[it];
            __nv_bfloat162 h01, h23, l01, l23;
            h01.x = __float2bfloat16(v.x); l01.x = __float2bfloat16(v.x - __bfloat162float(h01.x));
            h01.y = __float2bfloat16(v.y); l01.y = __float2bfloat16(v.y - __bfloat162float(h01.y));
            h23.x = __float2bfloat16(v.z); l23.x = __float2bfloat16(v.z - __bfloat162float(h23.x));
            h23.y = __float2bfloat16(v.w); l23.y = __float2bfloat16(v.w - __bfloat162float(h23.y));
            uint2 uh, ul;
            uh.x = *(uint32_t*)&h01; uh.y = *(uint32_t*)&h23;
            ul.x = *(uint32_t*)&l01; ul.y = *(uint32_t*)&l23;
            *(uint2*)&Ash[r * PAD + c4 * 4] = uh;
            *(uint2*)&Asl[r * PAD + c4 * 4] = ul;
        }
#pragma unroll
        for (int it = 0; it < 2; it++) {
            int idx = tid + it * 512;
            int r = idx >> 3, c8 = idx & 7;
            *(uint4*)&Bsh[r * PAD + c8 * 8] = bReg[it];
            *(uint4*)&Bsl[r * PAD + c8 * 8] = bReg[it + 2];
        }
    };

    int nchunks = Ktot / KC;
    loadA(0);
    loadB(0);
    storeStage(0);
    __syncthreads();

    for (int c = 0; c < nchunks; c++) {
        int buf = c & 1;
        bool more = (c + 1 < nchunks);
        if (more) { loadA(c + 1); loadB(c + 1); }   // global loads in flight

        char* base = smem + buf * STAGE;
        __nv_bfloat16* Ash = (__nv_bfloat16*)(base + AH_OFF);
        __nv_bfloat16* Asl = (__nv_bfloat16*)(base + AL_OFF);
        __nv_bfloat16* Bsh = (__nv_bfloat16*)(base + BH_OFF);
        __nv_bfloat16* Bsl = (__nv_bfloat16*)(base + BL_OFF);

#pragma unroll
        for (int ks = 0; ks < KC / 16; ks++) {
            int kk = ks * 16;
            uint32_t ah[2][4], al[2][4];
#pragma unroll
            for (int mt = 0; mt < 2; mt++) {
                int ar = wm * 32 + mt * 16 + g;
                int cA = kk + tig * 2;
                ah[mt][0] = *(const uint32_t*)&Ash[ar * PAD + cA];
                ah[mt][1] = *(const uint32_t*)&Ash[(ar + 8) * PAD + cA];
                ah[mt][2] = *(const uint32_t*)&Ash[ar * PAD + cA + 8];
                ah[mt][3] = *(const uint32_t*)&Ash[(ar + 8) * PAD + cA + 8];
                al[mt][0] = *(const uint32_t*)&Asl[ar * PAD + cA];
                al[mt][1] = *(const uint32_t*)&Asl[(ar + 8) * PAD + cA];
                al[mt][2] = *(const uint32_t*)&Asl[ar * PAD + cA + 8];
                al[mt][3] = *(const uint32_t*)&Asl[(ar + 8) * PAD + cA + 8];
            }
#pragma unroll
            for (int nt = 0; nt < 4; nt++) {
                int bn = wn * 32 + nt * 8 + g;
                int cB = kk + tig * 2;
                uint32_t bh[2], bl[2];
                bh[0] = *(const uint32_t*)&Bsh[bn * PAD + cB];
                bh[1] = *(const uint32_t*)&Bsh[bn * PAD + cB + 8];
                bl[0] = *(const uint32_t*)&Bsl[bn * PAD + cB];
                bl[1] = *(const uint32_t*)&Bsl[bn * PAD + cB + 8];
#pragma unroll
                for (int mt = 0; mt < 2; mt++) {
                    mma16816(acc[mt][nt], ah[mt], bh);
                    mma16816(acc[mt][nt], ah[mt], bl);
                    mma16816(acc[mt][nt], al[mt], bh);
                }
            }
        }

        if (more) storeStage((c + 1) & 1);   // overlaps with this chunk's mma drain
        __syncthreads();                      // one barrier per chunk
    }

    // epilogue: fp32 out
#pragma unroll
    for (int mt = 0; mt < 2; mt++) {
        int r1 = row0 + wm * 32 + mt * 16 + g;
        int r2 = r1 + 8;
#pragma unroll
        for (int nt = 0; nt < 4; nt++) {
            int cl = wn * 32 + nt * 8 + tig * 2;
            int cg = n0 + cl;
            float b0v = bias[cg], b1v = bias[cg + 1];
            float v00 = acc[mt][nt][0] + b0v, v01 = acc[mt][nt][1] + b1v;
            float v10 = acc[mt][nt][2] + b0v, v11 = acc[mt][nt][3] + b1v;
            if (relu) {
                v00 = fmaxf(v00, 0.f); v01 = fmaxf(v01, 0.f);
                v10 = fmaxf(v10, 0.f); v11 = fmaxf(v11, 0.f);
            }
            if (r1 < NN) *(float2*)&O[(size_t)r1 * ldo + co + cg] = make_float2(v00, v01);
            if (r2 < NN) *(float2*)&O[(size_t)r2 * ldo + co + cg] = make_float2(v10, v11);
        }
    }
}

// ---------------- launch ----------------
extern "C" void kernel_launch(void* const* d_in, const int* in_sizes, int n_in,
                              void* d_out, int out_size) {
    const float* x0  = (const float*)d_in[0];
    const float* x1  = (const float*)d_in[1];
    const void*  eix = d_in[2];
    const float* Wl0 = (const float*)d_in[3];
    const float* Wr0 = (const float*)d_in[4];
    const float* b0  = (const float*)d_in[5];
    const float* Wl1 = (const float*)d_in[6];
    const float* Wr1 = (const float*)d_in[7];
    const float* b1  = (const float*)d_in[8];
    const float* Wlm = (const float*)d_in[9];
    const float* Wrm = (const float*)d_in[10];
    const float* bm  = (const float*)d_in[11];
    const float* Wlo = (const float*)d_in[12];
    const float* Wro = (const float*)d_in[13];
    const float* bo  = (const float*)d_in[14];
    float* out = (float*)d_out;

    cudaFuncSetAttribute(gemm_mma, cudaFuncAttributeMaxDynamicSharedMemorySize, SMEM_SZ);

    float *a0f, *a1f, *hf, *amf, *h2f, *pq, *biasf;
    __nv_bfloat16 *WT0h, *WT0l, *WT1h, *WT1l, *WTmh, *WTml, *WTfh, *WTfl;
    cudaGetSymbolAddress((void**)&a0f, g_a0f);
    cudaGetSymbolAddress((void**)&a1f, g_a1f);
    cudaGetSymbolAddress((void**)&hf,  g_hf);
    cudaGetSymbolAddress((void**)&amf, g_amf);
    cudaGetSymbolAddress((void**)&h2f, g_h2f);
    cudaGetSymbolAddress((void**)&pq,  g_pq);
    cudaGetSymbolAddress((void**)&biasf, g_biasf);
    cudaGetSymbolAddress((void**)&WT0h, g_WT0h); cudaGetSymbolAddress((void**)&WT0l, g_WT0l);
    cudaGetSymbolAddress((void**)&WT1h, g_WT1h); cudaGetSymbolAddress((void**)&WT1l, g_WT1l);
    cudaGetSymbolAddress((void**)&WTmh, g_WTmh); cudaGetSymbolAddress((void**)&WTml, g_WTml);
    cudaGetSymbolAddress((void**)&WTfh, g_WTfh); cudaGetSymbolAddress((void**)&WTfl, g_WTfl);

    // CSR build
    sniff_kernel<<<1, 1>>>((const int*)eix);
    zero_kernel<<<(NN + 255) / 256, 256>>>();
    deg_kernel<<<(EE + 255) / 256, 256>>>(eix);
    scan1_kernel<<<SCANB, 1024>>>();
    scan2_kernel<<<1, 32>>>();
    scan3_kernel<<<SCANB, 1024>>>();
    scatter_kernel<<<(EE + 255) / 256, 256>>>(eix);

    // weight prep
    wprep_kernel<<<(128 * 256 + 256 * 512 + 255) / 256, 256>>>(Wl0, Wr0, Wl1, Wr1, Wlm, Wrm, Wlo, Wro, bo);

    const int GX = (NN + 127) / 128;  // 391

    // layer 0 + 1 fused into one launch (z selects branch)
    agg_xx_kernel<<<NN, 128>>>(x0, x1);
    gemm_mma<<<dim3(GX, 1, 2), 512, SMEM_SZ>>>(
        a0f, x0, WT0h, WT0l, b0, 0,
        a1f, x1, WT1h, WT1l, b1, 128,
        128, 128, 128, 256, 1, hf, 256);

    // middle conv
    agg_mid_kernel<<<NN, 256>>>(hf);
    gemm_mma<<<dim3(GX, 2, 1), 512, SMEM_SZ>>>(
        amf, hf, WTmh, WTml, bm, 0,
        amf, hf, WTmh, WTml, bm, 0,
        256, 256, 256, 512, 1, h2f, 256);

    // final conv (project-then-aggregate): pq = h2 @ [Wlo | Wro] + biasf
    gemm_mma<<<dim3(GX, 1, 1), 512, SMEM_SZ>>>(
        h2f, h2f, WTfh, WTfl, biasf, 0,
        h2f, h2f, WTfh, WTfl, biasf, 0,
        256, 256, 256, 256, 0, pq, 128);
    final_kernel<<<NN, 64>>>(out);
}

// round 15
// speedup vs baseline: 1.2408x; 1.1308x over previous
#include <cuda_runtime.h>
#include <cuda_fp16.h>
#include <cstdint>

constexpr int NN = 50000;
constexpr int EE = 800000;
constexpr int KC = 64;
constexpr int SCANB = 49;

// ---------------- device scratch ----------------
__device__ int   g_is64;
__device__ int   g_deg[NN];
__device__ int   g_cursor[NN];
__device__ int   g_ptr[NN + 1];
__device__ float g_invdeg[NN];
__device__ int   g_edges[EE];
__device__ int   g_part[SCANB];
__device__ int   g_boff[SCANB];

__device__ float g_a0f[(size_t)NN * 128];
__device__ float g_a1f[(size_t)NN * 128];
__device__ float g_hf [(size_t)NN * 256];
__device__ float g_amf[(size_t)NN * 256];
__device__ float g_h2f[(size_t)NN * 256];
__device__ float g_pq [(size_t)NN * 128];

// transposed + split fp16 weights: WT[n][k] = W[k][n], concat over Ktot
__device__ __half g_WT0h[128 * 256];
__device__ __half g_WT0l[128 * 256];
__device__ __half g_WT1h[128 * 256];
__device__ __half g_WT1l[128 * 256];
__device__ __half g_WTmh[256 * 512];
__device__ __half g_WTml[256 * 512];
__device__ __half g_WTfh[128 * 256];
__device__ __half g_WTfl[128 * 256];
__device__ float  g_biasf[128];

// ---------------- edge dtype sniff ----------------
__global__ void sniff_kernel(const int* __restrict__ e32) {
    int is64 = 1;
    for (int i = 1; i < 64; i += 2)
        if (e32[i] != 0) { is64 = 0; break; }
    g_is64 = is64;
}
__device__ __forceinline__ int load_edge(const void* e, int idx) {
    if (g_is64) return (int)((const long long*)e)[idx];
    return ((const int*)e)[idx];
}

// ---------------- CSR build ----------------
__global__ void zero_kernel() {
    int i = blockIdx.x * blockDim.x + threadIdx.x;
    if (i < NN) { g_deg[i] = 0; g_cursor[i] = 0; }
}
__global__ void deg_kernel(const void* __restrict__ e) {
    int i = blockIdx.x * blockDim.x + threadIdx.x;
    if (i >= EE) return;
    atomicAdd(&g_deg[load_edge(e, EE + i)], 1);
}
__global__ void scan1_kernel() {
    __shared__ int sm[1024];
    int t = threadIdx.x;
    int i = blockIdx.x * 1024 + t;
    sm[t] = (i < NN) ? g_deg[i] : 0;
    __syncthreads();
    for (int off = 512; off; off >>= 1) {
        if (t < off) sm[t] += sm[t + off];
        __syncthreads();
    }
    if (t == 0) g_part[blockIdx.x] = sm[0];
}
__global__ void scan2_kernel() {
    if (threadIdx.x == 0) {
        int run = 0;
        for (int b = 0; b < SCANB; b++) { g_boff[b] = run; run += g_part[b]; }
        g_ptr[NN] = EE;
    }
}
__global__ void scan3_kernel() {
    __shared__ int sm[1024];
    int t = threadIdx.x;
    int i = blockIdx.x * 1024 + t;
    int v = (i < NN) ? g_deg[i] : 0;
    sm[t] = v;
    __syncthreads();
    for (int off = 1; off < 1024; off <<= 1) {
        int u = (t >= off) ? sm[t - off] : 0;
        __syncthreads();
        if (t >= off) sm[t] += u;
        __syncthreads();
    }
    if (i < NN) {
        g_ptr[i] = g_boff[blockIdx.x] + sm[t] - v;
        g_invdeg[i] = 1.0f / (float)max(v, 1);
    }
}
__global__ void scatter_kernel(const void* __restrict__ e) {
    int i = blockIdx.x * blockDim.x + threadIdx.x;
    if (i >= EE) return;
    int src = load_edge(e, i);
    int dst = load_edge(e, EE + i);
    g_edges[g_ptr[dst] + atomicAdd(&g_cursor[dst], 1)] = src;
}

// ---------------- weight prep: fp16 hi/lo split ----------------
__device__ __forceinline__ void split2h(float v, __half& h, __half& l) {
    h = __float2half_rn(v);
    l = __float2half_rn(v - __half2float(h));
}
__global__ void wprep_kernel(const float* __restrict__ Wl0, const float* __restrict__ Wr0,
                             const float* __restrict__ Wl1, const float* __restrict__ Wr1,
                             const float* __restrict__ Wlm, const float* __restrict__ Wrm,
                             const float* __restrict__ Wlo, const float* __restrict__ Wro,
                             const float* __restrict__ bo) {
    int i = blockIdx.x * blockDim.x + threadIdx.x;
    if (i < 128 * 256) {
        int n = i >> 8, k = i & 255;
        float w0 = (k < 128) ? Wl0[k * 128 + n] : Wr0[(k - 128) * 128 + n];
        float w1 = (k < 128) ? Wl1[k * 128 + n] : Wr1[(k - 128) * 128 + n];
        split2h(w0, g_WT0h[i], g_WT0l[i]);
        split2h(w1, g_WT1h[i], g_WT1l[i]);
        float wf = (n < 64) ? Wlo[k * 64 + n] : Wro[k * 64 + (n - 64)];
        split2h(wf, g_WTfh[i], g_WTfl[i]);
        if (i < 128) g_biasf[i] = (i < 64) ? 0.f : bo[i - 64];
    }
    int j = i - 128 * 256;
    if (j >= 0 && j < 256 * 512) {
        int n = j >> 9, k = j & 511;
        float w = (k < 256) ? Wlm[k * 256 + n] : Wrm[(k - 256) * 256 + n];
        split2h(w, g_WTmh[j], g_WTml[j]);
    }
}

// ---------------- aggregation ----------------
__global__ __launch_bounds__(128) void agg_xx_kernel(
    const float* __restrict__ x0, const float* __restrict__ x1) {
    __shared__ float red0[4][128];
    __shared__ float red1[4][128];
    int node = blockIdx.x;
    int t = threadIdx.x;
    int lane = t & 31, w = t >> 5;
    int s = g_ptr[node], e = g_ptr[node + 1];
    float4 a0 = make_float4(0.f, 0.f, 0.f, 0.f), a1 = a0;
    for (int i = s + w; i < e; i += 4) {
        int src = g_edges[i];
        float4 v0 = __ldg((const float4*)(x0 + (size_t)src * 128) + lane);
        float4 v1 = __ldg((const float4*)(x1 + (size_t)src * 128) + lane);
        a0.x += v0.x; a0.y += v0.y; a0.z += v0.z; a0.w += v0.w;
        a1.x += v1.x; a1.y += v1.y; a1.z += v1.z; a1.w += v1.w;
    }
    *(float4*)&red0[w][lane * 4] = a0;
    *(float4*)&red1[w][lane * 4] = a1;
    __syncthreads();
    float inv = g_invdeg[node];
    float s0 = (red0[0][t] + red0[1][t]) + (red0[2][t] + red0[3][t]);
    float s1 = (red1[0][t] + red1[1][t]) + (red1[2][t] + red1[3][t]);
    g_a0f[(size_t)node * 128 + t] = s0 * inv;
    g_a1f[(size_t)node * 128 + t] = s1 * inv;
}

__global__ __launch_bounds__(256) void agg_mid_kernel(const float* __restrict__ X) {
    __shared__ float red[4][256];
    int node = blockIdx.x;
    int t = threadIdx.x;
    int lane = t & 31, w = t >> 5;
    int el = w >> 1, half = w & 1;
    int s = g_ptr[node], e = g_ptr[node + 1];
    float4 a = make_float4(0.f, 0.f, 0.f, 0.f);
    for (int i = s + el; i < e; i += 4) {
        int src = g_edges[i];
        float4 v = __ldg((const float4*)(X + (size_t)src * 256) + half * 32 + lane);
        a.x += v.x; a.y += v.y; a.z += v.z; a.w += v.w;
    }
    *(float4*)&red[el][half * 128 + lane * 4] = a;
    __syncthreads();
    float sum = (red[0][t] + red[1][t]) + (red[2][t] + red[3][t]);
    g_amf[(size_t)node * 256 + t] = sum * g_invdeg[node];
}

__global__ __launch_bounds__(64) void final_kernel(float* __restrict__ out) {
    __shared__ float red[4][64];
    int node = blockIdx.x;
    int t = threadIdx.x;
    int el = t >> 4, c4 = t & 15;
    int s = g_ptr[node], e = g_ptr[node + 1];
    float4 a = make_float4(0.f, 0.f, 0.f, 0.f);
    for (int i = s + el; i < e; i += 4) {
        int src = g_edges[i];
        float4 v = __ldg((const float4*)(g_pq + (size_t)src * 128) + c4);
        a.x += v.x; a.y += v.y; a.z += v.z; a.w += v.w;
    }
    *(float4*)&red[el][c4 * 4] = a;
    __syncthreads();
    float sum = (red[0][t] + red[1][t]) + (red[2][t] + red[3][t]);
    out[(size_t)node * 64 + t] = sum * g_invdeg[node] + g_pq[(size_t)node * 128 + 64 + t];
}

// ---------------- mma.sync fp16 GEMM (A single fp16, B split hi/lo) ----------------
// C[row, n] = sum_k A[row, k] * WT[n, k]; A = (A1|A2) fp32 concat over k.
// fp32 emulated: Ah*(Bh + Bl), fp32 accumulate. 2 mmas per tile.
// A rounding error 2^-12 dominates -> rel_err ~2e-4 over 4 layers (budget 1e-3).
// 512 threads = 16 warps (4x4); CTA tile 128x128; warp tile 32x32.
// Double-buffered SMEM, one __syncthreads per chunk.
#define PAD 72
#define AS_OFF 0
#define BH_OFF (128 * PAD * 2)
#define BL_OFF (2 * 128 * PAD * 2)
#define STAGE  (3 * 128 * PAD * 2)
#define SMEM_SZ (2 * STAGE)

__device__ __forceinline__ void mma16816(float* d, const uint32_t* a, const uint32_t* b) {
    asm volatile(
        "mma.sync.aligned.m16n8k16.row.col.f32.f16.f16.f32 "
        "{%0,%1,%2,%3}, {%4,%5,%6,%7}, {%8,%9}, {%0,%1,%2,%3};"
        : "+f"(d[0]), "+f"(d[1]), "+f"(d[2]), "+f"(d[3])
        : "r"(a[0]), "r"(a[1]), "r"(a[2]), "r"(a[3]), "r"(b[0]), "r"(b[1]));
}

__global__ __launch_bounds__(512) void gemm_mma(
    const float* __restrict__ A1a, const float* __restrict__ A2a,
    const __half* __restrict__ WTha, const __half* __restrict__ WTla,
    const float* __restrict__ biasa, int coa,
    const float* __restrict__ A1b, const float* __restrict__ A2b,
    const __half* __restrict__ WThb, const __half* __restrict__ WTlb,
    const float* __restrict__ biasb, int cob,
    int lda1, int lda2, int K1, int Ktot,
    int relu, float* __restrict__ O, int ldo)
{
    extern __shared__ char smem[];

    const float* A1 = A1a; const float* A2 = A2a;
    const __half* WTh = WTha; const __half* WTl = WTla;
    const float* bias = biasa; int co = coa;
    if (blockIdx.z) { A1 = A1b; A2 = A2b; WTh = WThb; WTl = WTlb; bias = biasb; co = cob; }

    int tid = threadIdx.x;
    int wid = tid >> 5;
    int lane = tid & 31;
    int g = lane >> 2, tig = lane & 3;
    int wm = wid >> 2, wn = wid & 3;
    int row0 = blockIdx.x * 128;
    int n0 = blockIdx.y * 128;

    const __half* WThB = WTh + (size_t)n0 * Ktot;
    const __half* WTlB = WTl + (size_t)n0 * Ktot;

    float acc[2][4][4];
#pragma unroll
    for (int mt = 0; mt < 2; mt++)
#pragma unroll
        for (int nt = 0; nt < 4; nt++)
#pragma unroll
            for (int q = 0; q < 4; q++) acc[mt][nt][q] = 0.f;

    float4 aReg[4];
    uint4  bReg[4];
    int aRow[4];
#pragma unroll
    for (int it = 0; it < 4; it++) {
        int idx = tid + it * 512;
        aRow[it] = row0 + (idx >> 4);
    }

    auto loadA = [&](int c) {
        int kt = c * KC;
        const float* A; int lda, kb;
        if (kt < K1) { A = A1; lda = lda1; kb = kt; }
        else         { A = A2; lda = lda2; kb = kt - K1; }
#pragma unroll
        for (int it = 0; it < 4; it++) {
            int idx = tid + it * 512;
            int c4 = idx & 15;
            float4 v = make_float4(0.f, 0.f, 0.f, 0.f);
            if (aRow[it] < NN)
                v = __ldg((const float4*)(A + (size_t)aRow[it] * lda + kb) + c4);
            aReg[it] = v;
        }
    };
    auto loadB = [&](int c) {
        int kt = c * KC;
#pragma unroll
        for (int it = 0; it < 2; it++) {
            int idx = tid + it * 512;
            int r = idx >> 3, c8 = idx & 7;
            bReg[it]     = *(const uint4*)(WThB + (size_t)r * Ktot + kt + c8 * 8);
            bReg[it + 2] = *(const uint4*)(WTlB + (size_t)r * Ktot + kt + c8 * 8);
        }
    };
    auto storeStage = [&](int s) {
        char* base = smem + s * STAGE;
        __half* As  = (__half*)(base + AS_OFF);
        __half* Bsh = (__half*)(base + BH_OFF);
        __half* Bsl = (__half*)(base + BL_OFF);
#pragma unroll
        for (int it = 0; it < 4; it++) {
            int idx = tid + it * 512;
            int r = idx >> 4, c4 = idx & 15;
            float4 v = aReg[it];
            __half2 h01 = __floats2half2_rn(v.x, v.y);
            __half2 h23 = __floats2half2_rn(v.z, v.w);
            uint2 uh;
            uh.x = *(uint32_t*)&h01; uh.y = *(uint32_t*)&h23;
            *(uint2*)&As[r * PAD + c4 * 4] = uh;
        }
#pragma unroll
        for (int it = 0; it < 2; it++) {
            int idx = tid + it * 512;
            int r = idx >> 3, c8 = idx & 7;
            *(uint4*)&Bsh[r * PAD + c8 * 8] = bReg[it];
            *(uint4*)&Bsl[r * PAD + c8 * 8] = bReg[it + 2];
        }
    };

    int nchunks = Ktot / KC;
    loadA(0);
    loadB(0);
    storeStage(0);
    __syncthreads();

    for (int c = 0; c < nchunks; c++) {
        int buf = c & 1;
        bool more = (c + 1 < nchunks);
        if (more) { loadA(c + 1); loadB(c + 1); }

        char* base = smem + buf * STAGE;
        __half* As  = (__half*)(base + AS_OFF);
        __half* Bsh = (__half*)(base + BH_OFF);
        __half* Bsl = (__half*)(base + BL_OFF);

#pragma unroll
        for (int ks = 0; ks < KC / 16; ks++) {
            int kk = ks * 16;
            uint32_t ah[2][4];
#pragma unroll
            for (int mt = 0; mt < 2; mt++) {
                int ar = wm * 32 + mt * 16 + g;
                int cA = kk + tig * 2;
                ah[mt][0] = *(const uint32_t*)&As[ar * PAD + cA];
                ah[mt][1] = *(const uint32_t*)&As[(ar + 8) * PAD + cA];
                ah[mt][2] = *(const uint32_t*)&As[ar * PAD + cA + 8];
                ah[mt][3] = *(const uint32_t*)&As[(ar + 8) * PAD + cA + 8];
            }
#pragma unroll
            for (int nt = 0; nt < 4; nt++) {
                int bn = wn * 32 + nt * 8 + g;
                int cB = kk + tig * 2;
                uint32_t bh[2], bl[2];
                bh[0] = *(const uint32_t*)&Bsh[bn * PAD + cB];
                bh[1] = *(const uint32_t*)&Bsh[bn * PAD + cB + 8];
                bl[0] = *(const uint32_t*)&Bsl[bn * PAD + cB];
                bl[1] = *(const uint32_t*)&Bsl[bn * PAD + cB + 8];
#pragma unroll
                for (int mt = 0; mt < 2; mt++) {
                    mma16816(acc[mt][nt], ah[mt], bh);
                    mma16816(acc[mt][nt], ah[mt], bl);
                }
            }
        }

        if (more) storeStage((c + 1) & 1);
        __syncthreads();
    }

    // epilogue: fp32 out
#pragma unroll
    for (int mt = 0; mt < 2; mt++) {
        int r1 = row0 + wm * 32 + mt * 16 + g;
        int r2 = r1 + 8;
#pragma unroll
        for (int nt = 0; nt < 4; nt++) {
            int cl = wn * 32 + nt * 8 + tig * 2;
            int cg = n0 + cl;
            float b0v = bias[cg], b1v = bias[cg + 1];
            float v00 = acc[mt][nt][0] + b0v, v01 = acc[mt][nt][1] + b1v;
            float v10 = acc[mt][nt][2] + b0v, v11 = acc[mt][nt][3] + b1v;
            if (relu) {
                v00 = fmaxf(v00, 0.f); v01 = fmaxf(v01, 0.f);
                v10 = fmaxf(v10, 0.f); v11 = fmaxf(v11, 0.f);
            }
            if (r1 < NN) *(float2*)&O[(size_t)r1 * ldo + co + cg] = make_float2(v00, v01);
            if (r2 < NN) *(float2*)&O[(size_t)r2 * ldo + co + cg] = make_float2(v10, v11);
        }
    }
}

// ---------------- launch ----------------
extern "C" void kernel_launch(void* const* d_in, const int* in_sizes, int n_in,
                              void* d_out, int out_size) {
    const float* x0  = (const float*)d_in[0];
    const float* x1  = (const float*)d_in[1];
    const void*  eix = d_in[2];
    const float* Wl0 = (const float*)d_in[3];
    const float* Wr0 = (const float*)d_in[4];
    const float* b0  = (const float*)d_in[5];
    const float* Wl1 = (const float*)d_in[6];
    const float* Wr1 = (const float*)d_in[7];
    const float* b1  = (const float*)d_in[8];
    const float* Wlm = (const float*)d_in[9];
    const float* Wrm = (const float*)d_in[10];
    const float* bm  = (const float*)d_in[11];
    const float* Wlo = (const float*)d_in[12];
    const float* Wro = (const float*)d_in[13];
    const float* bo  = (const float*)d_in[14];
    float* out = (float*)d_out;

    cudaFuncSetAttribute(gemm_mma, cudaFuncAttributeMaxDynamicSharedMemorySize, SMEM_SZ);

    float *a0f, *a1f, *hf, *amf, *h2f, *pq, *biasf;
    __half *WT0h, *WT0l, *WT1h, *WT1l, *WTmh, *WTml, *WTfh, *WTfl;
    cudaGetSymbolAddress((void**)&a0f, g_a0f);
    cudaGetSymbolAddress((void**)&a1f, g_a1f);
    cudaGetSymbolAddress((void**)&hf,  g_hf);
    cudaGetSymbolAddress((void**)&amf, g_amf);
    cudaGetSymbolAddress((void**)&h2f, g_h2f);
    cudaGetSymbolAddress((void**)&pq,  g_pq);
    cudaGetSymbolAddress((void**)&biasf, g_biasf);
    cudaGetSymbolAddress((void**)&WT0h, g_WT0h); cudaGetSymbolAddress((void**)&WT0l, g_WT0l);
    cudaGetSymbolAddress((void**)&WT1h, g_WT1h); cudaGetSymbolAddress((void**)&WT1l, g_WT1l);
    cudaGetSymbolAddress((void**)&WTmh, g_WTmh); cudaGetSymbolAddress((void**)&WTml, g_WTml);
    cudaGetSymbolAddress((void**)&WTfh, g_WTfh); cudaGetSymbolAddress((void**)&WTfl, g_WTfl);

    // CSR build
    sniff_kernel<<<1, 1>>>((const int*)eix);
    zero_kernel<<<(NN + 255) / 256, 256>>>();
    deg_kernel<<<(EE + 255) / 256, 256>>>(eix);
    scan1_kernel<<<SCANB, 1024>>>();
    scan2_kernel<<<1, 32>>>();
    scan3_kernel<<<SCANB, 1024>>>();
    scatter_kernel<<<(EE + 255) / 256, 256>>>(eix);

    // weight prep
    wprep_kernel<<<(128 * 256 + 256 * 512 + 255) / 256, 256>>>(Wl0, Wr0, Wl1, Wr1, Wlm, Wrm, Wlo, Wro, bo);

    const int GX = (NN + 127) / 128;  // 391

    // layer 0 + 1 fused into one launch (z selects branch)
    agg_xx_kernel<<<NN, 128>>>(x0, x1);
    gemm_mma<<<dim3(GX, 1, 2), 512, SMEM_SZ>>>(
        a0f, x0, WT0h, WT0l, b0, 0,
        a1f, x1, WT1h, WT1l, b1, 128,
        128, 128, 128, 256, 1, hf, 256);

    // middle conv
    agg_mid_kernel<<<NN, 256>>>(hf);
    gemm_mma<<<dim3(GX, 2, 1), 512, SMEM_SZ>>>(
        amf, hf, WTmh, WTml, bm, 0,
        amf, hf, WTmh, WTml, bm, 0,
        256, 256, 256, 512, 1, h2f, 256);

    // final conv (project-then-aggregate): pq = h2 @ [Wlo | Wro] + biasf
    gemm_mma<<<dim3(GX, 1, 1), 512, SMEM_SZ>>>(
        h2f, h2f, WTfh, WTfl, biasf, 0,
        h2f, h2f, WTfh, WTfl, biasf, 0,
        256, 256, 256, 256, 0, pq, 128);
    final_kernel<<<NN, 64>>>(out);
}

// round 16
// speedup vs baseline: 1.3739x; 1.1072x over previous
#include <cuda_runtime.h>
#include <cuda_fp16.h>
#include <cstdint>

constexpr int NN = 50000;
constexpr int EE = 800000;
constexpr int KC = 64;
constexpr int SCANB = 49;

// ---------------- device scratch ----------------
__device__ int   g_is64;
__device__ int   g_deg[NN];
__device__ int   g_cursor[NN];
__device__ int   g_ptr[NN + 1];
__device__ float g_invdeg[NN];
__device__ int   g_edges[EE];
__device__ int   g_part[SCANB];
__device__ int   g_boff[SCANB];

__device__ float g_a0f[(size_t)NN * 128];
__device__ float g_a1f[(size_t)NN * 128];
__device__ float g_hf [(size_t)NN * 256];
__device__ float g_amf[(size_t)NN * 256];
__device__ float g_h2f[(size_t)NN * 256];
__device__ float g_pq [(size_t)NN * 128];

// transposed fp16 weights: WT[n][k] = W[k][n], concat over Ktot
__device__ __half g_WT0[128 * 256];
__device__ __half g_WT1[128 * 256];
__device__ __half g_WTm[256 * 512];
__device__ __half g_WTf[128 * 256];
__device__ float  g_biasf[128];

// ---------------- edge dtype sniff ----------------
__global__ void sniff_kernel(const int* __restrict__ e32) {
    int is64 = 1;
    for (int i = 1; i < 64; i += 2)
        if (e32[i] != 0) { is64 = 0; break; }
    g_is64 = is64;
}
__device__ __forceinline__ int load_edge(const void* e, int idx) {
    if (g_is64) return (int)((const long long*)e)[idx];
    return ((const int*)e)[idx];
}

// ---------------- CSR build ----------------
__global__ void zero_kernel() {
    int i = blockIdx.x * blockDim.x + threadIdx.x;
    if (i < NN) { g_deg[i] = 0; g_cursor[i] = 0; }
}
__global__ void deg_kernel(const void* __restrict__ e) {
    int i = blockIdx.x * blockDim.x + threadIdx.x;
    if (i >= EE) return;
    atomicAdd(&g_deg[load_edge(e, EE + i)], 1);
}
__global__ void scan1_kernel() {
    __shared__ int sm[1024];
    int t = threadIdx.x;
    int i = blockIdx.x * 1024 + t;
    sm[t] = (i < NN) ? g_deg[i] : 0;
    __syncthreads();
    for (int off = 512; off; off >>= 1) {
        if (t < off) sm[t] += sm[t + off];
        __syncthreads();
    }
    if (t == 0) g_part[blockIdx.x] = sm[0];
}
__global__ void scan2_kernel() {
    if (threadIdx.x == 0) {
        int run = 0;
        for (int b = 0; b < SCANB; b++) { g_boff[b] = run; run += g_part[b]; }
        g_ptr[NN] = EE;
    }
}
__global__ void scan3_kernel() {
    __shared__ int sm[1024];
    int t = threadIdx.x;
    int i = blockIdx.x * 1024 + t;
    int v = (i < NN) ? g_deg[i] : 0;
    sm[t] = v;
    __syncthreads();
    for (int off = 1; off < 1024; off <<= 1) {
        int u = (t >= off) ? sm[t - off] : 0;
        __syncthreads();
        if (t >= off) sm[t] += u;
        __syncthreads();
    }
    if (i < NN) {
        g_ptr[i] = g_boff[blockIdx.x] + sm[t] - v;
        g_invdeg[i] = 1.0f / (float)max(v, 1);
    }
}
__global__ void scatter_kernel(const void* __restrict__ e) {
    int i = blockIdx.x * blockDim.x + threadIdx.x;
    if (i >= EE) return;
    int src = load_edge(e, i);
    int dst = load_edge(e, EE + i);
    g_edges[g_ptr[dst] + atomicAdd(&g_cursor[dst], 1)] = src;
}

// ---------------- weight prep: single fp16 ----------------
__global__ void wprep_kernel(const float* __restrict__ Wl0, const float* __restrict__ Wr0,
                             const float* __restrict__ Wl1, const float* __restrict__ Wr1,
                             const float* __restrict__ Wlm, const float* __restrict__ Wrm,
                             const float* __restrict__ Wlo, const float* __restrict__ Wro,
                             const float* __restrict__ bo) {
    int i = blockIdx.x * blockDim.x + threadIdx.x;
    if (i < 128 * 256) {
        int n = i >> 8, k = i & 255;
        float w0 = (k < 128) ? Wl0[k * 128 + n] : Wr0[(k - 128) * 128 + n];
        float w1 = (k < 128) ? Wl1[k * 128 + n] : Wr1[(k - 128) * 128 + n];
        g_WT0[i] = __float2half_rn(w0);
        g_WT1[i] = __float2half_rn(w1);
        float wf = (n < 64) ? Wlo[k * 64 + n] : Wro[k * 64 + (n - 64)];
        g_WTf[i] = __float2half_rn(wf);
        if (i < 128) g_biasf[i] = (i < 64) ? 0.f : bo[i - 64];
    }
    int j = i - 128 * 256;
    if (j >= 0 && j < 256 * 512) {
        int n = j >> 9, k = j & 511;
        float w = (k < 256) ? Wlm[k * 256 + n] : Wrm[(k - 256) * 256 + n];
        g_WTm[j] = __float2half_rn(w);
    }
}

// ---------------- aggregation ----------------
__global__ __launch_bounds__(128) void agg_xx_kernel(
    const float* __restrict__ x0, const float* __restrict__ x1) {
    __shared__ float red0[4][128];
    __shared__ float red1[4][128];
    int node = blockIdx.x;
    int t = threadIdx.x;
    int lane = t & 31, w = t >> 5;
    int s = g_ptr[node], e = g_ptr[node + 1];
    float4 a0 = make_float4(0.f, 0.f, 0.f, 0.f), a1 = a0;
    for (int i = s + w; i < e; i += 4) {
        int src = g_edges[i];
        float4 v0 = __ldg((const float4*)(x0 + (size_t)src * 128) + lane);
        float4 v1 = __ldg((const float4*)(x1 + (size_t)src * 128) + lane);
        a0.x += v0.x; a0.y += v0.y; a0.z += v0.z; a0.w += v0.w;
        a1.x += v1.x; a1.y += v1.y; a1.z += v1.z; a1.w += v1.w;
    }
    *(float4*)&red0[w][lane * 4] = a0;
    *(float4*)&red1[w][lane * 4] = a1;
    __syncthreads();
    float inv = g_invdeg[node];
    float s0 = (red0[0][t] + red0[1][t]) + (red0[2][t] + red0[3][t]);
    float s1 = (red1[0][t] + red1[1][t]) + (red1[2][t] + red1[3][t]);
    g_a0f[(size_t)node * 128 + t] = s0 * inv;
    g_a1f[(size_t)node * 128 + t] = s1 * inv;
}

__global__ __launch_bounds__(256) void agg_mid_kernel(const float* __restrict__ X) {
    __shared__ float red[4][256];
    int node = blockIdx.x;
    int t = threadIdx.x;
    int lane = t & 31, w = t >> 5;
    int el = w >> 1, half = w & 1;
    int s = g_ptr[node], e = g_ptr[node + 1];
    float4 a = make_float4(0.f, 0.f, 0.f, 0.f);
    for (int i = s + el; i < e; i += 4) {
        int src = g_edges[i];
        float4 v = __ldg((const float4*)(X + (size_t)src * 256) + half * 32 + lane);
        a.x += v.x; a.y += v.y; a.z += v.z; a.w += v.w;
    }
    *(float4*)&red[el][half * 128 + lane * 4] = a;
    __syncthreads();
    float sum = (red[0][t] + red[1][t]) + (red[2][t] + red[3][t]);
    g_amf[(size_t)node * 256 + t] = sum * g_invdeg[node];
}

__global__ __launch_bounds__(64) void final_kernel(float* __restrict__ out) {
    __shared__ float red[4][64];
    int node = blockIdx.x;
    int t = threadIdx.x;
    int el = t >> 4, c4 = t & 15;
    int s = g_ptr[node], e = g_ptr[node + 1];
    float4 a = make_float4(0.f, 0.f, 0.f, 0.f);
    for (int i = s + el; i < e; i += 4) {
        int src = g_edges[i];
        float4 v = __ldg((const float4*)(g_pq + (size_t)src * 128) + c4);
        a.x += v.x; a.y += v.y; a.z += v.z; a.w += v.w;
    }
    *(float4*)&red[el][c4 * 4] = a;
    __syncthreads();
    float sum = (red[0][t] + red[1][t]) + (red[2][t] + red[3][t]);
    out[(size_t)node * 64 + t] = sum * g_invdeg[node] + g_pq[(size_t)node * 128 + 64 + t];
}

// ---------------- mma.sync fp16 GEMM (single-precision fp16 both sides) ----------------
// C[row, n] = sum_k A[row, k] * WT[n, k]; A = (A1|A2) fp32 concat over k,
// rounded to fp16 in-kernel; W pre-rounded to fp16. 1 mma per tile, fp32 accum.
// Rounding error ~2^-12 each side -> rel_err ~4.5e-4 (budget 1e-3).
// 512 threads = 16 warps (4x4); CTA tile 128x128; warp tile 32x32.
// Double-buffered SMEM, one __syncthreads per chunk.
#define PAD 72
#define AS_OFF 0
#define BS_OFF (128 * PAD * 2)
#define STAGE  (2 * 128 * PAD * 2)
#define SMEM_SZ (2 * STAGE)

__device__ __forceinline__ void mma16816(float* d, const uint32_t* a, const uint32_t* b) {
    asm volatile(
        "mma.sync.aligned.m16n8k16.row.col.f32.f16.f16.f32 "
        "{%0,%1,%2,%3}, {%4,%5,%6,%7}, {%8,%9}, {%0,%1,%2,%3};"
        : "+f"(d[0]), "+f"(d[1]), "+f"(d[2]), "+f"(d[3])
        : "r"(a[0]), "r"(a[1]), "r"(a[2]), "r"(a[3]), "r"(b[0]), "r"(b[1]));
}

__global__ __launch_bounds__(512) void gemm_mma(
    const float* __restrict__ A1a, const float* __restrict__ A2a,
    const __half* __restrict__ WTa, const float* __restrict__ biasa, int coa,
    const float* __restrict__ A1b, const float* __restrict__ A2b,
    const __half* __restrict__ WTb, const float* __restrict__ biasb, int cob,
    int lda1, int lda2, int K1, int Ktot,
    int relu, float* __restrict__ O, int ldo)
{
    extern __shared__ char smem[];

    const float* A1 = A1a; const float* A2 = A2a;
    const __half* WT = WTa;
    const float* bias = biasa; int co = coa;
    if (blockIdx.z) { A1 = A1b; A2 = A2b; WT = WTb; bias = biasb; co = cob; }

    int tid = threadIdx.x;
    int wid = tid >> 5;
    int lane = tid & 31;
    int g = lane >> 2, tig = lane & 3;
    int wm = wid >> 2, wn = wid & 3;
    int row0 = blockIdx.x * 128;
    int n0 = blockIdx.y * 128;

    const __half* WTB = WT + (size_t)n0 * Ktot;

    float acc[2][4][4];
#pragma unroll
    for (int mt = 0; mt < 2; mt++)
#pragma unroll
        for (int nt = 0; nt < 4; nt++)
#pragma unroll
            for (int q = 0; q < 4; q++) acc[mt][nt][q] = 0.f;

    float4 aReg[4];
    uint4  bReg[2];
    int aRow[4];
#pragma unroll
    for (int it = 0; it < 4; it++) {
        int idx = tid + it * 512;
        aRow[it] = row0 + (idx >> 4);
    }

    auto loadA = [&](int c) {
        int kt = c * KC;
        const float* A; int lda, kb;
        if (kt < K1) { A = A1; lda = lda1; kb = kt; }
        else         { A = A2; lda = lda2; kb = kt - K1; }
#pragma unroll
        for (int it = 0; it < 4; it++) {
            int idx = tid + it * 512;
            int c4 = idx & 15;
            float4 v = make_float4(0.f, 0.f, 0.f, 0.f);
            if (aRow[it] < NN)
                v = __ldg((const float4*)(A + (size_t)aRow[it] * lda + kb) + c4);
            aReg[it] = v;
        }
    };
    auto loadB = [&](int c) {
        int kt = c * KC;
#pragma unroll
        for (int it = 0; it < 2; it++) {
            int idx = tid + it * 512;
            int r = idx >> 3, c8 = idx & 7;
            bReg[it] = *(const uint4*)(WTB + (size_t)r * Ktot + kt + c8 * 8);
        }
    };
    auto storeStage = [&](int s) {
        char* base = smem + s * STAGE;
        __half* As = (__half*)(base + AS_OFF);
        __half* Bs = (__half*)(base + BS_OFF);
#pragma unroll
        for (int it = 0; it < 4; it++) {
            int idx = tid + it * 512;
            int r = idx >> 4, c4 = idx & 15;
            float4 v = aReg[it];
            __half2 h01 = __floats2half2_rn(v.x, v.y);
            __half2 h23 = __floats2half2_rn(v.z, v.w);
            uint2 uh;
            uh.x = *(uint32_t*)&h01; uh.y = *(uint32_t*)&h23;
            *(uint2*)&As[r * PAD + c4 * 4] = uh;
        }
#pragma unroll
        for (int it = 0; it < 2; it++) {
            int idx = tid + it * 512;
            int r = idx >> 3, c8 = idx & 7;
            *(uint4*)&Bs[r * PAD + c8 * 8] = bReg[it];
        }
    };

    int nchunks = Ktot / KC;
    loadA(0);
    loadB(0);
    storeStage(0);
    __syncthreads();

    for (int c = 0; c < nchunks; c++) {
        int buf = c & 1;
        bool more = (c + 1 < nchunks);
        if (more) { loadA(c + 1); loadB(c + 1); }

        char* base = smem + buf * STAGE;
        __half* As = (__half*)(base + AS_OFF);
        __half* Bs = (__half*)(base + BS_OFF);

#pragma unroll
        for (int ks = 0; ks < KC / 16; ks++) {
            int kk = ks * 16;
            uint32_t ah[2][4];
#pragma unroll
            for (int mt = 0; mt < 2; mt++) {
                int ar = wm * 32 + mt * 16 + g;
                int cA = kk + tig * 2;
                ah[mt][0] = *(const uint32_t*)&As[ar * PAD + cA];
                ah[mt][1] = *(const uint32_t*)&As[(ar + 8) * PAD + cA];
                ah[mt][2] = *(const uint32_t*)&As[ar * PAD + cA + 8];
                ah[mt][3] = *(const uint32_t*)&As[(ar + 8) * PAD + cA + 8];
            }
#pragma unroll
            for (int nt = 0; nt < 4; nt++) {
                int bn = wn * 32 + nt * 8 + g;
                int cB = kk + tig * 2;
                uint32_t bh[2];
                bh[0] = *(const uint32_t*)&Bs[bn * PAD + cB];
                bh[1] = *(const uint32_t*)&Bs[bn * PAD + cB + 8];
#pragma unroll
                for (int mt = 0; mt < 2; mt++) {
                    mma16816(acc[mt][nt], ah[mt], bh);
                }
            }
        }

        if (more) storeStage((c + 1) & 1);
        __syncthreads();
    }

    // epilogue: fp32 out
#pragma unroll
    for (int mt = 0; mt < 2; mt++) {
        int r1 = row0 + wm * 32 + mt * 16 + g;
        int r2 = r1 + 8;
#pragma unroll
        for (int nt = 0; nt < 4; nt++) {
            int cl = wn * 32 + nt * 8 + tig * 2;
            int cg = n0 + cl;
            float b0v = bias[cg], b1v = bias[cg + 1];
            float v00 = acc[mt][nt][0] + b0v, v01 = acc[mt][nt][1] + b1v;
            float v10 = acc[mt][nt][2] + b0v, v11 = acc[mt][nt][3] + b1v;
            if (relu) {
                v00 = fmaxf(v00, 0.f); v01 = fmaxf(v01, 0.f);
                v10 = fmaxf(v10, 0.f); v11 = fmaxf(v11, 0.f);
            }
            if (r1 < NN) *(float2*)&O[(size_t)r1 * ldo + co + cg] = make_float2(v00, v01);
            if (r2 < NN) *(float2*)&O[(size_t)r2 * ldo + co + cg] = make_float2(v10, v11);
        }
    }
}

// ---------------- launch ----------------
extern "C" void kernel_launch(void* const* d_in, const int* in_sizes, int n_in,
                              void* d_out, int out_size) {
    const float* x0  = (const float*)d_in[0];
    const float* x1  = (const float*)d_in[1];
    const void*  eix = d_in[2];
    const float* Wl0 = (const float*)d_in[3];
    const float* Wr0 = (const float*)d_in[4];
    const float* b0  = (const float*)d_in[5];
    const float* Wl1 = (const float*)d_in[6];
    const float* Wr1 = (const float*)d_in[7];
    const float* b1  = (const float*)d_in[8];
    const float* Wlm = (const float*)d_in[9];
    const float* Wrm = (const float*)d_in[10];
    const float* bm  = (const float*)d_in[11];
    const float* Wlo = (const float*)d_in[12];
    const float* Wro = (const float*)d_in[13];
    const float* bo  = (const float*)d_in[14];
    float* out = (float*)d_out;

    cudaFuncSetAttribute(gemm_mma, cudaFuncAttributeMaxDynamicSharedMemorySize, SMEM_SZ);

    float *a0f, *a1f, *hf, *amf, *h2f, *pq, *biasf;
    __half *WT0, *WT1, *WTm, *WTf;
    cudaGetSymbolAddress((void**)&a0f, g_a0f);
    cudaGetSymbolAddress((void**)&a1f, g_a1f);
    cudaGetSymbolAddress((void**)&hf,  g_hf);
    cudaGetSymbolAddress((void**)&amf, g_amf);
    cudaGetSymbolAddress((void**)&h2f, g_h2f);
    cudaGetSymbolAddress((void**)&pq,  g_pq);
    cudaGetSymbolAddress((void**)&biasf, g_biasf);
    cudaGetSymbolAddress((void**)&WT0, g_WT0);
    cudaGetSymbolAddress((void**)&WT1, g_WT1);
    cudaGetSymbolAddress((void**)&WTm, g_WTm);
    cudaGetSymbolAddress((void**)&WTf, g_WTf);

    // CSR build
    sniff_kernel<<<1, 1>>>((const int*)eix);
    zero_kernel<<<(NN + 255) / 256, 256>>>();
    deg_kernel<<<(EE + 255) / 256, 256>>>(eix);
    scan1_kernel<<<SCANB, 1024>>>();
    scan2_kernel<<<1, 32>>>();
    scan3_kernel<<<SCANB, 1024>>>();
    scatter_kernel<<<(EE + 255) / 256, 256>>>(eix);

    // weight prep
    wprep_kernel<<<(128 * 256 + 256 * 512 + 255) / 256, 256>>>(Wl0, Wr0, Wl1, Wr1, Wlm, Wrm, Wlo, Wro, bo);

    const int GX = (NN + 127) / 128;  // 391

    // layer 0 + 1 fused into one launch (z selects branch)
    agg_xx_kernel<<<NN, 128>>>(x0, x1);
    gemm_mma<<<dim3(GX, 1, 2), 512, SMEM_SZ>>>(
        a0f, x0, WT0, b0, 0,
        a1f, x1, WT1, b1, 128,
        128, 128, 128, 256, 1, hf, 256);

    // middle conv
    agg_mid_kernel<<<NN, 256>>>(hf);
    gemm_mma<<<dim3(GX, 2, 1), 512, SMEM_SZ>>>(
        amf, hf, WTm, bm, 0,
        amf, hf, WTm, bm, 0,
        256, 256, 256, 512, 1, h2f, 256);

    // final conv (project-then-aggregate): pq = h2 @ [Wlo | Wro] + biasf
    gemm_mma<<<dim3(GX, 1, 1), 512, SMEM_SZ>>>(
        h2f, h2f, WTf, biasf, 0,
        h2f, h2f, WTf, biasf, 0,
        256, 256, 256, 256, 0, pq, 128);
    final_kernel<<<NN, 64>>>(out);
}

// round 17
// speedup vs baseline: 1.3758x; 1.0014x over previous
#include <cuda_runtime.h>
#include <cuda_fp16.h>
#include <cstdint>

constexpr int NN = 50000;
constexpr int EE = 800000;
constexpr int KC = 64;
constexpr int SCANB = 49;

// ---------------- device scratch ----------------
__device__ int   g_is64;
__device__ int   g_deg[NN];
__device__ int   g_cursor[NN];
__device__ int   g_ptr[NN + 1];
__device__ float g_invdeg[NN];
__device__ int   g_edges[EE];
__device__ int   g_part[SCANB];
__device__ int   g_boff[SCANB];

__device__ float g_a0f[(size_t)NN * 128];
__device__ float g_a1f[(size_t)NN * 128];
__device__ float g_hf [(size_t)NN * 256];
__device__ float g_amf[(size_t)NN * 256];
__device__ float g_h2f[(size_t)NN * 256];
__device__ float g_pq [(size_t)NN * 128];

// fp16 gather mirrors
__device__ __half g_x0h [(size_t)NN * 128];
__device__ __half g_x1h [(size_t)NN * 128];
__device__ __half g_hf16[(size_t)NN * 256];
__device__ __half g_p16 [(size_t)NN * 64];

// transposed fp16 weights: WT[n][k] = W[k][n], concat over Ktot
__device__ __half g_WT0[128 * 256];
__device__ __half g_WT1[128 * 256];
__device__ __half g_WTm[256 * 512];
__device__ __half g_WTf[128 * 256];
__device__ float  g_biasf[128];

// ---------------- edge dtype sniff ----------------
__global__ void sniff_kernel(const int* __restrict__ e32) {
    int is64 = 1;
    for (int i = 1; i < 64; i += 2)
        if (e32[i] != 0) { is64 = 0; break; }
    g_is64 = is64;
}
__device__ __forceinline__ int load_edge(const void* e, int idx) {
    if (g_is64) return (int)((const long long*)e)[idx];
    return ((const int*)e)[idx];
}

// ---------------- CSR build ----------------
__global__ void zero_kernel() {
    int i = blockIdx.x * blockDim.x + threadIdx.x;
    if (i < NN) { g_deg[i] = 0; g_cursor[i] = 0; }
}
__global__ void deg_kernel(const void* __restrict__ e) {
    int i = blockIdx.x * blockDim.x + threadIdx.x;
    if (i >= EE) return;
    atomicAdd(&g_deg[load_edge(e, EE + i)], 1);
}
__global__ void scan1_kernel() {
    __shared__ int sm[1024];
    int t = threadIdx.x;
    int i = blockIdx.x * 1024 + t;
    sm[t] = (i < NN) ? g_deg[i] : 0;
    __syncthreads();
    for (int off = 512; off; off >>= 1) {
        if (t < off) sm[t] += sm[t + off];
        __syncthreads();
    }
    if (t == 0) g_part[blockIdx.x] = sm[0];
}
__global__ void scan2_kernel() {
    if (threadIdx.x == 0) {
        int run = 0;
        for (int b = 0; b < SCANB; b++) { g_boff[b] = run; run += g_part[b]; }
        g_ptr[NN] = EE;
    }
}
__global__ void scan3_kernel() {
    __shared__ int sm[1024];
    int t = threadIdx.x;
    int i = blockIdx.x * 1024 + t;
    int v = (i < NN) ? g_deg[i] : 0;
    sm[t] = v;
    __syncthreads();
    for (int off = 1; off < 1024; off <<= 1) {
        int u = (t >= off) ? sm[t - off] : 0;
        __syncthreads();
        if (t >= off) sm[t] += u;
        __syncthreads();
    }
    if (i < NN) {
        g_ptr[i] = g_boff[blockIdx.x] + sm[t] - v;
        g_invdeg[i] = 1.0f / (float)max(v, 1);
    }
}
__global__ void scatter_kernel(const void* __restrict__ e) {
    int i = blockIdx.x * blockDim.x + threadIdx.x;
    if (i >= EE) return;
    int src = load_edge(e, i);
    int dst = load_edge(e, EE + i);
    g_edges[g_ptr[dst] + atomicAdd(&g_cursor[dst], 1)] = src;
}

// ---------------- input fp16 mirror ----------------
__global__ void convx_kernel(const float* __restrict__ x0, const float* __restrict__ x1) {
    int i = blockIdx.x * blockDim.x + threadIdx.x;   // one float4 per thread
    if (i >= NN * 32) return;
    float4 v0 = __ldg((const float4*)x0 + i);
    float4 v1 = __ldg((const float4*)x1 + i);
    __half2 a0 = __floats2half2_rn(v0.x, v0.y), b0 = __floats2half2_rn(v0.z, v0.w);
    __half2 a1 = __floats2half2_rn(v1.x, v1.y), b1 = __floats2half2_rn(v1.z, v1.w);
    uint2 u0, u1;
    u0.x = *(uint32_t*)&a0; u0.y = *(uint32_t*)&b0;
    u1.x = *(uint32_t*)&a1; u1.y = *(uint32_t*)&b1;
    *(uint2*)(g_x0h + (size_t)i * 4) = u0;
    *(uint2*)(g_x1h + (size_t)i * 4) = u1;
}

// ---------------- weight prep: single fp16 ----------------
__global__ void wprep_kernel(const float* __restrict__ Wl0, const float* __restrict__ Wr0,
                             const float* __restrict__ Wl1, const float* __restrict__ Wr1,
                             const float* __restrict__ Wlm, const float* __restrict__ Wrm,
                             const float* __restrict__ Wlo, const float* __restrict__ Wro,
                             const float* __restrict__ bo) {
    int i = blockIdx.x * blockDim.x + threadIdx.x;
    if (i < 128 * 256) {
        int n = i >> 8, k = i & 255;
        float w0 = (k < 128) ? Wl0[k * 128 + n] : Wr0[(k - 128) * 128 + n];
        float w1 = (k < 128) ? Wl1[k * 128 + n] : Wr1[(k - 128) * 128 + n];
        g_WT0[i] = __float2half_rn(w0);
        g_WT1[i] = __float2half_rn(w1);
        float wf = (n < 64) ? Wlo[k * 64 + n] : Wro[k * 64 + (n - 64)];
        g_WTf[i] = __float2half_rn(wf);
        if (i < 128) g_biasf[i] = (i < 64) ? 0.f : bo[i - 64];
    }
    int j = i - 128 * 256;
    if (j >= 0 && j < 256 * 512) {
        int n = j >> 9, k = j & 511;
        float w = (k < 256) ? Wlm[k * 256 + n] : Wrm[(k - 256) * 256 + n];
        g_WTm[j] = __float2half_rn(w);
    }
}

// ---------------- aggregation (fp16 gathers, fp32 accumulate) ----------------
__device__ __forceinline__ void acc4h(float* a, uint2 u) {
    __half2 h0 = *(__half2*)&u.x, h1 = *(__half2*)&u.y;
    float2 f0 = __half22float2(h0), f1 = __half22float2(h1);
    a[0] += f0.x; a[1] += f0.y; a[2] += f1.x; a[3] += f1.y;
}

__global__ __launch_bounds__(128) void agg_xx_kernel() {
    __shared__ float red0[4][128];
    __shared__ float red1[4][128];
    int node = blockIdx.x;
    int t = threadIdx.x;
    int lane = t & 31, w = t >> 5;
    int s = g_ptr[node], e = g_ptr[node + 1];
    float a0[4] = {0.f, 0.f, 0.f, 0.f}, a1[4] = {0.f, 0.f, 0.f, 0.f};
    for (int i = s + w; i < e; i += 4) {
        int src = g_edges[i];
        acc4h(a0, __ldg((const uint2*)(g_x0h + (size_t)src * 128) + lane));
        acc4h(a1, __ldg((const uint2*)(g_x1h + (size_t)src * 128) + lane));
    }
    *(float4*)&red0[w][lane * 4] = *(float4*)a0;
    *(float4*)&red1[w][lane * 4] = *(float4*)a1;
    __syncthreads();
    float inv = g_invdeg[node];
    float s0 = (red0[0][t] + red0[1][t]) + (red0[2][t] + red0[3][t]);
    float s1 = (red1[0][t] + red1[1][t]) + (red1[2][t] + red1[3][t]);
    g_a0f[(size_t)node * 128 + t] = s0 * inv;
    g_a1f[(size_t)node * 128 + t] = s1 * inv;
}

__global__ __launch_bounds__(256) void agg_mid_kernel() {
    __shared__ float red[4][256];
    int node = blockIdx.x;
    int t = threadIdx.x;
    int lane = t & 31, w = t >> 5;
    int el = w >> 1, half = w & 1;
    int s = g_ptr[node], e = g_ptr[node + 1];
    float a[4] = {0.f, 0.f, 0.f, 0.f};
    for (int i = s + el; i < e; i += 4) {
        int src = g_edges[i];
        acc4h(a, __ldg((const uint2*)(g_hf16 + (size_t)src * 256 + half * 128) + lane));
    }
    *(float4*)&red[el][half * 128 + lane * 4] = *(float4*)a;
    __syncthreads();
    float sum = (red[0][t] + red[1][t]) + (red[2][t] + red[3][t]);
    g_amf[(size_t)node * 256 + t] = sum * g_invdeg[node];
}

__global__ __launch_bounds__(64) void final_kernel(float* __restrict__ out) {
    __shared__ float red[4][64];
    int node = blockIdx.x;
    int t = threadIdx.x;
    int el = t >> 4, c4 = t & 15;
    int s = g_ptr[node], e = g_ptr[node + 1];
    float a[4] = {0.f, 0.f, 0.f, 0.f};
    for (int i = s + el; i < e; i += 4) {
        int src = g_edges[i];
        acc4h(a, __ldg((const uint2*)(g_p16 + (size_t)src * 64) + c4));
    }
    *(float4*)&red[el][c4 * 4] = *(float4*)a;
    __syncthreads();
    float sum = (red[0][t] + red[1][t]) + (red[2][t] + red[3][t]);
    out[(size_t)node * 64 + t] = sum * g_invdeg[node] + g_pq[(size_t)node * 128 + 64 + t];
}

// ---------------- mma.sync fp16 GEMM ----------------
// C[row, n] = sum_k A[row, k] * WT[n, k]; 1 mma/tile, fp32 accum.
// Optional fp16 epilogue mirror: cols cg < o16lim also stored to O16 (row stride ld16).
#define PAD 72
#define AS_OFF 0
#define BS_OFF (128 * PAD * 2)
#define STAGE  (2 * 128 * PAD * 2)
#define SMEM_SZ (2 * STAGE)

__device__ __forceinline__ void mma16816(float* d, const uint32_t* a, const uint32_t* b) {
    asm volatile(
        "mma.sync.aligned.m16n8k16.row.col.f32.f16.f16.f32 "
        "{%0,%1,%2,%3}, {%4,%5,%6,%7}, {%8,%9}, {%0,%1,%2,%3};"
        : "+f"(d[0]), "+f"(d[1]), "+f"(d[2]), "+f"(d[3])
        : "r"(a[0]), "r"(a[1]), "r"(a[2]), "r"(a[3]), "r"(b[0]), "r"(b[1]));
}

__global__ __launch_bounds__(512) void gemm_mma(
    const float* __restrict__ A1a, const float* __restrict__ A2a,
    const __half* __restrict__ WTa, const float* __restrict__ biasa, int coa,
    const float* __restrict__ A1b, const float* __restrict__ A2b,
    const __half* __restrict__ WTb, const float* __restrict__ biasb, int cob,
    int lda1, int lda2, int K1, int Ktot,
    int relu, float* __restrict__ O, int ldo,
    __half* __restrict__ O16, int ld16, int o16lim)
{
    extern __shared__ char smem[];

    const float* A1 = A1a; const float* A2 = A2a;
    const __half* WT = WTa;
    const float* bias = biasa; int co = coa;
    if (blockIdx.z) { A1 = A1b; A2 = A2b; WT = WTb; bias = biasb; co = cob; }

    int tid = threadIdx.x;
    int wid = tid >> 5;
    int lane = tid & 31;
    int g = lane >> 2, tig = lane & 3;
    int wm = wid >> 2, wn = wid & 3;
    int row0 = blockIdx.x * 128;
    int n0 = blockIdx.y * 128;

    const __half* WTB = WT + (size_t)n0 * Ktot;

    float acc[2][4][4];
#pragma unroll
    for (int mt = 0; mt < 2; mt++)
#pragma unroll
        for (int nt = 0; nt < 4; nt++)
#pragma unroll
            for (int q = 0; q < 4; q++) acc[mt][nt][q] = 0.f;

    float4 aReg[4];
    uint4  bReg[2];
    int aRow[4];
#pragma unroll
    for (int it = 0; it < 4; it++) {
        int idx = tid + it * 512;
        aRow[it] = row0 + (idx >> 4);
    }

    auto loadA = [&](int c) {
        int kt = c * KC;
        const float* A; int lda, kb;
        if (kt < K1) { A = A1; lda = lda1; kb = kt; }
        else         { A = A2; lda = lda2; kb = kt - K1; }
#pragma unroll
        for (int it = 0; it < 4; it++) {
            int idx = tid + it * 512;
            int c4 = idx & 15;
            float4 v = make_float4(0.f, 0.f, 0.f, 0.f);
            if (aRow[it] < NN)
                v = __ldg((const float4*)(A + (size_t)aRow[it] * lda + kb) + c4);
            aReg[it] = v;
        }
    };
    auto loadB = [&](int c) {
        int kt = c * KC;
#pragma unroll
        for (int it = 0; it < 2; it++) {
            int idx = tid + it * 512;
            int r = idx >> 3, c8 = idx & 7;
            bReg[it] = *(const uint4*)(WTB + (size_t)r * Ktot + kt + c8 * 8);
        }
    };
    auto storeStage = [&](int s) {
        char* base = smem + s * STAGE;
        __half* As = (__half*)(base + AS_OFF);
        __half* Bs = (__half*)(base + BS_OFF);
#pragma unroll
        for (int it = 0; it < 4; it++) {
            int idx = tid + it * 512;
            int r = idx >> 4, c4 = idx & 15;
            float4 v = aReg[it];
            __half2 h01 = __floats2half2_rn(v.x, v.y);
            __half2 h23 = __floats2half2_rn(v.z, v.w);
            uint2 uh;
            uh.x = *(uint32_t*)&h01; uh.y = *(uint32_t*)&h23;
            *(uint2*)&As[r * PAD + c4 * 4] = uh;
        }
#pragma unroll
        for (int it = 0; it < 2; it++) {
            int idx = tid + it * 512;
            int r = idx >> 3, c8 = idx & 7;
            *(uint4*)&Bs[r * PAD + c8 * 8] = bReg[it];
        }
    };

    int nchunks = Ktot / KC;
    loadA(0);
    loadB(0);
    storeStage(0);
    __syncthreads();

    for (int c = 0; c < nchunks; c++) {
        int buf = c & 1;
        bool more = (c + 1 < nchunks);
        if (more) { loadA(c + 1); loadB(c + 1); }

        char* base = smem + buf * STAGE;
        __half* As = (__half*)(base + AS_OFF);
        __half* Bs = (__half*)(base + BS_OFF);

#pragma unroll
        for (int ks = 0; ks < KC / 16; ks++) {
            int kk = ks * 16;
            uint32_t ah[2][4];
#pragma unroll
            for (int mt = 0; mt < 2; mt++) {
                int ar = wm * 32 + mt * 16 + g;
                int cA = kk + tig * 2;
                ah[mt][0] = *(const uint32_t*)&As[ar * PAD + cA];
                ah[mt][1] = *(const uint32_t*)&As[(ar + 8) * PAD + cA];
                ah[mt][2] = *(const uint32_t*)&As[ar * PAD + cA + 8];
                ah[mt][3] = *(const uint32_t*)&As[(ar + 8) * PAD + cA + 8];
            }
#pragma unroll
            for (int nt = 0; nt < 4; nt++) {
                int bn = wn * 32 + nt * 8 + g;
                int cB = kk + tig * 2;
                uint32_t bh[2];
                bh[0] = *(const uint32_t*)&Bs[bn * PAD + cB];
                bh[1] = *(const uint32_t*)&Bs[bn * PAD + cB + 8];
#pragma unroll
                for (int mt = 0; mt < 2; mt++) {
                    mma16816(acc[mt][nt], ah[mt], bh);
                }
            }
        }

        if (more) storeStage((c + 1) & 1);
        __syncthreads();
    }

    // epilogue: fp32 out + optional fp16 mirror
#pragma unroll
    for (int mt = 0; mt < 2; mt++) {
        int r1 = row0 + wm * 32 + mt * 16 + g;
        int r2 = r1 + 8;
#pragma unroll
        for (int nt = 0; nt < 4; nt++) {
            int cl = wn * 32 + nt * 8 + tig * 2;
            int cg = n0 + cl;
            float b0v = bias[cg], b1v = bias[cg + 1];
            float v00 = acc[mt][nt][0] + b0v, v01 = acc[mt][nt][1] + b1v;
            float v10 = acc[mt][nt][2] + b0v, v11 = acc[mt][nt][3] + b1v;
            if (relu) {
                v00 = fmaxf(v00, 0.f); v01 = fmaxf(v01, 0.f);
                v10 = fmaxf(v10, 0.f); v11 = fmaxf(v11, 0.f);
            }
            if (r1 < NN) {
                *(float2*)&O[(size_t)r1 * ldo + co + cg] = make_float2(v00, v01);
                if (O16 && cg < o16lim) {
                    __half2 h = __floats2half2_rn(v00, v01);
                    *(__half2*)&O16[(size_t)r1 * ld16 + co + cg] = h;
                }
            }
            if (r2 < NN) {
                *(float2*)&O[(size_t)r2 * ldo + co + cg] = make_float2(v10, v11);
                if (O16 && cg < o16lim) {
                    __half2 h = __floats2half2_rn(v10, v11);
                    *(__half2*)&O16[(size_t)r2 * ld16 + co + cg] = h;
                }
            }
        }
    }
}

// ---------------- launch ----------------
extern "C" void kernel_launch(void* const* d_in, const int* in_sizes, int n_in,
                              void* d_out, int out_size) {
    const float* x0  = (const float*)d_in[0];
    const float* x1  = (const float*)d_in[1];
    const void*  eix = d_in[2];
    const float* Wl0 = (const float*)d_in[3];
    const float* Wr0 = (const float*)d_in[4];
    const float* b0  = (const float*)d_in[5];
    const float* Wl1 = (const float*)d_in[6];
    const float* Wr1 = (const float*)d_in[7];
    const float* b1  = (const float*)d_in[8];
    const float* Wlm = (const float*)d_in[9];
    const float* Wrm = (const float*)d_in[10];
    const float* bm  = (const float*)d_in[11];
    const float* Wlo = (const float*)d_in[12];
    const float* Wro = (const float*)d_in[13];
    const float* bo  = (const float*)d_in[14];
    float* out = (float*)d_out;

    cudaFuncSetAttribute(gemm_mma, cudaFuncAttributeMaxDynamicSharedMemorySize, SMEM_SZ);

    float *a0f, *a1f, *hf, *amf, *h2f, *pq, *biasf;
    __half *WT0, *WT1, *WTm, *WTf, *hf16, *p16;
    cudaGetSymbolAddress((void**)&a0f, g_a0f);
    cudaGetSymbolAddress((void**)&a1f, g_a1f);
    cudaGetSymbolAddress((void**)&hf,  g_hf);
    cudaGetSymbolAddress((void**)&amf, g_amf);
    cudaGetSymbolAddress((void**)&h2f, g_h2f);
    cudaGetSymbolAddress((void**)&pq,  g_pq);
    cudaGetSymbolAddress((void**)&biasf, g_biasf);
    cudaGetSymbolAddress((void**)&WT0, g_WT0);
    cudaGetSymbolAddress((void**)&WT1, g_WT1);
    cudaGetSymbolAddress((void**)&WTm, g_WTm);
    cudaGetSymbolAddress((void**)&WTf, g_WTf);
    cudaGetSymbolAddress((void**)&hf16, g_hf16);
    cudaGetSymbolAddress((void**)&p16,  g_p16);

    // CSR build
    sniff_kernel<<<1, 1>>>((const int*)eix);
    zero_kernel<<<(NN + 255) / 256, 256>>>();
    deg_kernel<<<(EE + 255) / 256, 256>>>(eix);
    scan1_kernel<<<SCANB, 1024>>>();
    scan2_kernel<<<1, 32>>>();
    scan3_kernel<<<SCANB, 1024>>>();
    scatter_kernel<<<(EE + 255) / 256, 256>>>(eix);

    // input fp16 mirrors + weight prep
    convx_kernel<<<(NN * 32 + 255) / 256, 256>>>(x0, x1);
    wprep_kernel<<<(128 * 256 + 256 * 512 + 255) / 256, 256>>>(Wl0, Wr0, Wl1, Wr1, Wlm, Wrm, Wlo, Wro, bo);

    const int GX = (NN + 127) / 128;  // 391

    // layer 0 + 1 fused (z selects branch); epilogue mirrors into hf16
    agg_xx_kernel<<<NN, 128>>>();
    gemm_mma<<<dim3(GX, 1, 2), 512, SMEM_SZ>>>(
        a0f, x0, WT0, b0, 0,
        a1f, x1, WT1, b1, 128,
        128, 128, 128, 256, 1, hf, 256, hf16, 256, 128);

    // middle conv (no fp16 mirror needed for h2f)
    agg_mid_kernel<<<NN, 256>>>();
    gemm_mma<<<dim3(GX, 2, 1), 512, SMEM_SZ>>>(
        amf, hf, WTm, bm, 0,
        amf, hf, WTm, bm, 0,
        256, 256, 256, 512, 1, h2f, 256, nullptr, 0, 0);

    // final conv: pq = h2 @ [Wlo | Wro] + biasf; P half mirrored into p16
    gemm_mma<<<dim3(GX, 1, 1), 512, SMEM_SZ>>>(
        h2f, h2f, WTf, biasf, 0,
        h2f, h2f, WTf, biasf, 0,
        256, 256, 256, 256, 0, pq, 128, p16, 64, 64);
    final_kernel<<<NN, 64>>>(out);
}